// round 1
// baseline (speedup 1.0000x reference)
#include <cuda_runtime.h>
#include <math.h>

// ---------------- problem constants ----------------
#define BATCH 4
#define SEQ   2048
#define CDIM  1024
#define NH    16
#define NHKV  4
#define HD    64
#define TOK   (BATCH*SEQ)          // 8192

// ---------------- scratch (device globals; no allocation allowed) ----------
__device__ float g_qp[TOK*CDIM];          // q projection [tok, 1024]
__device__ float g_kp[TOK*NHKV*HD];       // k projection [tok, 256]
__device__ float g_vp[TOK*NHKV*HD];       // v projection [tok, 256]
__device__ float g_q [BATCH*NH*SEQ*HD];   // [b,h,n,d] after norm+rope*1.5
__device__ float g_k [BATCH*NHKV*SEQ*HD]; // [b,hkv,n,d] after norm+rope
__device__ float g_v [BATCH*NHKV*SEQ*HD]; // [b,hkv,n,d]
__device__ float g_y [TOK*CDIM];          // attention output [tok, h*64+d]

// ---------------- generic tiled SGEMM: C[M,N] = A[M,K] @ B[K,N] ------------
// All dims multiples of tile sizes for this problem (M=8192, N in {1024,256},
// K=1024), so no boundary guards.
#define BM 128
#define BN 128
#define BK 16
#define TM 8
#define TN 8

__global__ __launch_bounds__(256) void sgemm_kernel(
    const float* __restrict__ A, const float* __restrict__ Bmat,
    float* __restrict__ C, int M, int Np, int K)
{
    __shared__ float As[BK][BM];
    __shared__ float Bs[BK][BN];

    int tid = threadIdx.x;
    int br = blockIdx.y, bc = blockIdx.x;
    const float* Ab = A + (size_t)br * BM * K;
    const float* Bb = Bmat + (size_t)bc * BN;

    float acc[TM][TN];
#pragma unroll
    for (int i = 0; i < TM; i++)
#pragma unroll
        for (int j = 0; j < TN; j++) acc[i][j] = 0.f;

    int tr = tid / 16;        // 0..15
    int tc = tid % 16;        // 0..15

    int aRow = tid / 4;           // 0..63
    int aCol = (tid % 4) * 4;     // 0,4,8,12
    int bRow = tid / 32;          // 0..7
    int bCol = (tid % 32) * 4;    // 0..124

    for (int k0 = 0; k0 < K; k0 += BK) {
#pragma unroll
        for (int i = 0; i < 2; i++) {
            float4 t = *(const float4*)(Ab + (size_t)(aRow + i*64) * K + k0 + aCol);
            As[aCol+0][aRow + i*64] = t.x;
            As[aCol+1][aRow + i*64] = t.y;
            As[aCol+2][aRow + i*64] = t.z;
            As[aCol+3][aRow + i*64] = t.w;
        }
#pragma unroll
        for (int i = 0; i < 2; i++) {
            float4 t = *(const float4*)(Bb + (size_t)(k0 + bRow + i*8) * Np + bCol);
            *(float4*)&Bs[bRow + i*8][bCol] = t;
        }
        __syncthreads();

#pragma unroll
        for (int kk = 0; kk < BK; kk++) {
            float ra[TM], rb[TN];
            *(float4*)&ra[0] = *(const float4*)&As[kk][tr*TM];
            *(float4*)&ra[4] = *(const float4*)&As[kk][tr*TM + 4];
            *(float4*)&rb[0] = *(const float4*)&Bs[kk][tc*TN];
            *(float4*)&rb[4] = *(const float4*)&Bs[kk][tc*TN + 4];
#pragma unroll
            for (int i = 0; i < TM; i++)
#pragma unroll
                for (int j = 0; j < TN; j++)
                    acc[i][j] += ra[i] * rb[j];
        }
        __syncthreads();
    }

    float* Cb = C + (size_t)(br*BM + tr*TM) * Np + bc*BN + tc*TN;
#pragma unroll
    for (int i = 0; i < TM; i++) {
        *(float4*)(Cb + (size_t)i * Np)     = make_float4(acc[i][0], acc[i][1], acc[i][2], acc[i][3]);
        *(float4*)(Cb + (size_t)i * Np + 4) = make_float4(acc[i][4], acc[i][5], acc[i][6], acc[i][7]);
    }
}

// ---------------- pack: RMSNorm + RoPE (+gain) + layout transpose ----------
// one warp per (token, slot) where slot: 0..15 q heads, 16..19 k heads, 20..23 v heads
__global__ __launch_bounds__(256) void pack_kernel()
{
    int w    = (blockIdx.x * 256 + threadIdx.x) >> 5;
    int lane = threadIdx.x & 31;
    int t    = w / 24;
    int slot = w - t * 24;
    int b = t / SEQ;
    int n = t - b * SEQ;

    float v0, v1;
    float* dst;
    bool dorope;
    float gain = 1.0f;

    if (slot < 16) {
        const float* src = g_qp + (size_t)t * CDIM + slot * HD;
        v0 = src[lane]; v1 = src[lane + 32];
        dst = g_q + (((size_t)(b * NH + slot)) * SEQ + n) * HD;
        dorope = true; gain = 1.5f;
    } else if (slot < 20) {
        int h = slot - 16;
        const float* src = g_kp + (size_t)t * (NHKV*HD) + h * HD;
        v0 = src[lane]; v1 = src[lane + 32];
        dst = g_k + (((size_t)(b * NHKV + h)) * SEQ + n) * HD;
        dorope = true;
    } else {
        int h = slot - 20;
        const float* src = g_vp + (size_t)t * (NHKV*HD) + h * HD;
        v0 = src[lane]; v1 = src[lane + 32];
        dst = g_v + (((size_t)(b * NHKV + h)) * SEQ + n) * HD;
        dorope = false;
    }

    if (dorope) {
        float ss = v0*v0 + v1*v1;
#pragma unroll
        for (int o = 16; o; o >>= 1) ss += __shfl_xor_sync(0xffffffffu, ss, o);
        float r = rsqrtf(ss * (1.0f/64.0f) + 1.1920929e-7f);
        v0 *= r; v1 *= r;
        // inv_freq = 10000^(-lane/32)
        float inv_freq = powf(10000.0f, -(float)lane * (1.0f/32.0f));
        float ang = (float)n * inv_freq;
        float sv, cv;
        sincosf(ang, &sv, &cv);                 // precise path (args up to 2047 rad)
        float o0 = v0*cv - v1*sv;
        float o1 = v1*cv + v0*sv;
        v0 = o0 * gain; v1 = o1 * gain;
    }
    dst[lane] = v0;
    dst[lane + 32] = v1;
}

// ---------------- causal flash attention -----------------------------------
// block = (qtile, head, batch); 128 threads = 128 query rows; 64-key smem tiles
#define QTILE 128
#define KTILE 64
#define CHUNK 32

__global__ __launch_bounds__(128) void attn_kernel()
{
    __shared__ float Ks[KTILE*HD];   // 16 KB
    __shared__ float Vs[KTILE*HD];   // 16 KB

    int qt = blockIdx.x, h = blockIdx.y, b = blockIdx.z;
    int r = threadIdx.x;
    int qrow = qt * QTILE + r;
    int hkv = h >> 2;                 // repeat_interleave: q head h -> kv head h/4

    const float* qptr  = g_q + (((size_t)(b*NH   + h  )) * SEQ + qrow) * HD;
    const float* kbase = g_k +  ((size_t)(b*NHKV + hkv)) * SEQ * HD;
    const float* vbase = g_v +  ((size_t)(b*NHKV + hkv)) * SEQ * HD;

    float q[HD];
#pragma unroll
    for (int d = 0; d < HD; d += 4) {
        float4 t4 = *(const float4*)(qptr + d);
        q[d] = t4.x; q[d+1] = t4.y; q[d+2] = t4.z; q[d+3] = t4.w;
    }

    float acc[HD];
#pragma unroll
    for (int d = 0; d < HD; d++) acc[d] = 0.f;
    float m = -1e30f, l = 0.f;

    int ntiles = (qt + 1) * (QTILE / KTILE);   // causal: only tiles up to the diagonal
    for (int kt = 0; kt < ntiles; kt++) {
        int k0 = kt * KTILE;
        __syncthreads();
        // load K,V tiles: 4096 floats each, 128 threads -> 8 float4 per thread
#pragma unroll
        for (int i = 0; i < (KTILE*HD)/(128*4); i++) {
            int idx = (i * 128 + r) * 4;
            *(float4*)&Ks[idx] = *(const float4*)&kbase[(size_t)k0 * HD + idx];
            *(float4*)&Vs[idx] = *(const float4*)&vbase[(size_t)k0 * HD + idx];
        }
        __syncthreads();

#pragma unroll
        for (int ch = 0; ch < KTILE/CHUNK; ch++) {
            int base = k0 + ch * CHUNK;
            if (base > qrow) continue;          // fully masked chunk

            float s[CHUNK];
#pragma unroll
            for (int j = 0; j < CHUNK; j++) {
                const float4* kp = (const float4*)&Ks[(ch*CHUNK + j) * HD];
                float s0=0.f, s1=0.f, s2=0.f, s3=0.f;
#pragma unroll
                for (int d4 = 0; d4 < HD/4; d4++) {
                    float4 kv = kp[d4];
                    s0 += q[d4*4+0] * kv.x;
                    s1 += q[d4*4+1] * kv.y;
                    s2 += q[d4*4+2] * kv.z;
                    s3 += q[d4*4+3] * kv.w;
                }
                s[j] = (s0 + s1) + (s2 + s3);
            }

            float mloc = m;
#pragma unroll
            for (int j = 0; j < CHUNK; j++) {
                s[j] = (base + j <= qrow) ? s[j] * 0.125f : -1e30f;
                mloc = fmaxf(mloc, s[j]);
            }
            float corr = __expf(m - mloc);
            m = mloc;
            l *= corr;
#pragma unroll
            for (int d = 0; d < HD; d++) acc[d] *= corr;

#pragma unroll
            for (int j = 0; j < CHUNK; j++) {
                float p = __expf(s[j] - mloc);
                l += p;
                const float4* vp4 = (const float4*)&Vs[(ch*CHUNK + j) * HD];
#pragma unroll
                for (int d4 = 0; d4 < HD/4; d4++) {
                    float4 vv = vp4[d4];
                    acc[d4*4+0] += p * vv.x;
                    acc[d4*4+1] += p * vv.y;
                    acc[d4*4+2] += p * vv.z;
                    acc[d4*4+3] += p * vv.w;
                }
            }
        }
    }

    float invl = 1.0f / l;
    float* y = g_y + (((size_t)(b*SEQ + qrow)) * NH + h) * HD;
#pragma unroll
    for (int d4 = 0; d4 < HD/4; d4++) {
        float4 o;
        o.x = acc[d4*4+0] * invl;
        o.y = acc[d4*4+1] * invl;
        o.z = acc[d4*4+2] * invl;
        o.w = acc[d4*4+3] * invl;
        ((float4*)y)[d4] = o;
    }
}

// ---------------- launch ----------------------------------------------------
extern "C" void kernel_launch(void* const* d_in, const int* in_sizes, int n_in,
                              void* d_out, int out_size)
{
    const float* x  = (const float*)d_in[0];
    const float* wq = (const float*)d_in[1];
    const float* wk = (const float*)d_in[2];
    const float* wv = (const float*)d_in[3];
    const float* wo = (const float*)d_in[4];
    float* out = (float*)d_out;

    float *qp, *kp, *vp, *yy;
    cudaGetSymbolAddress((void**)&qp, g_qp);
    cudaGetSymbolAddress((void**)&kp, g_kp);
    cudaGetSymbolAddress((void**)&vp, g_vp);
    cudaGetSymbolAddress((void**)&yy, g_y);

    // QKV projections
    dim3 gq(CDIM/BN, TOK/BM);                 // (8, 64)
    dim3 gkv((NHKV*HD)/BN, TOK/BM);           // (2, 64)
    sgemm_kernel<<<gq, 256>>>(x, wq, qp, TOK, CDIM, CDIM);
    sgemm_kernel<<<gkv, 256>>>(x, wk, kp, TOK, NHKV*HD, CDIM);
    sgemm_kernel<<<gkv, 256>>>(x, wv, vp, TOK, NHKV*HD, CDIM);

    // RMSNorm + RoPE + transpose (one warp per token-head task; 8192*24 warps)
    pack_kernel<<<(TOK*24)/8, 256>>>();

    // causal SDPA
    dim3 ga(SEQ/QTILE, NH, BATCH);            // (16, 16, 4)
    attn_kernel<<<ga, 128>>>();

    // output projection
    sgemm_kernel<<<gq, 256>>>(yy, wo, out, TOK, CDIM, CDIM);
}

// round 3
// speedup vs baseline: 1.1926x; 1.1926x over previous
#include <cuda_runtime.h>
#include <math.h>
#include <stdint.h>

// ---------------- problem constants ----------------
#define BATCH 4
#define SEQ   2048
#define CDIM  1024
#define NH    16
#define NHKV  4
#define HD    64
#define TOK   (BATCH*SEQ)          // 8192
#define GK    1024                 // K dim of every GEMM

// ---------------- scratch (device globals; no allocation allowed) ----------
__device__ float g_qp[TOK*CDIM];
__device__ float g_kp[TOK*NHKV*HD];
__device__ float g_vp[TOK*NHKV*HD];
__device__ float g_q [BATCH*NH*SEQ*HD];
__device__ float g_k [BATCH*NHKV*SEQ*HD];
__device__ float g_v [BATCH*NHKV*SEQ*HD];
__device__ float g_y [TOK*CDIM];
__device__ float g_wqT[CDIM*CDIM];         // [N,K] transposed weights
__device__ float g_wkT[NHKV*HD*CDIM];
__device__ float g_wvT[NHKV*HD*CDIM];
__device__ float g_woT[CDIM*CDIM];

// ---------------- helpers ----------------
__device__ __forceinline__ uint32_t f2tf32(float f) {
    uint32_t r;
    asm("cvt.rna.tf32.f32 %0, %1;" : "=r"(r) : "f"(f));
    return r;
}
__device__ __forceinline__ void mma_tf32(float& d0, float& d1, float& d2, float& d3,
                                         uint32_t a0, uint32_t a1, uint32_t a2, uint32_t a3,
                                         uint32_t b0, uint32_t b1) {
    asm volatile(
        "mma.sync.aligned.m16n8k8.row.col.f32.tf32.tf32.f32 "
        "{%0,%1,%2,%3}, {%4,%5,%6,%7}, {%8,%9}, {%0,%1,%2,%3};"
        : "+f"(d0), "+f"(d1), "+f"(d2), "+f"(d3)
        : "r"(a0), "r"(a1), "r"(a2), "r"(a3), "r"(b0), "r"(b1));
}

// ---------------- weight transpose: D[c][r] = S[r][c] ----------------------
__global__ __launch_bounds__(256) void transpose_kernel(
    const float* __restrict__ S, float* __restrict__ D, int R, int Ccols)
{
    __shared__ float t[32][33];
    int bx = blockIdx.x * 32, by = blockIdx.y * 32;
#pragma unroll
    for (int i = 0; i < 32; i += 8)
        t[threadIdx.y + i][threadIdx.x] = S[(size_t)(by + threadIdx.y + i) * Ccols + bx + threadIdx.x];
    __syncthreads();
#pragma unroll
    for (int i = 0; i < 32; i += 8)
        D[(size_t)(bx + threadIdx.y + i) * R + by + threadIdx.x] = t[threadIdx.x][threadIdx.y + i];
}

// ---------------- tf32 mma.sync GEMM: C[M,Np] = A[M,1024] @ Bt[Np,1024]^T ---
// CTA tile 128x128x16, 256 threads (8 warps, 2x4 warp grid, warp tile 64x32).
#define BKQ 16
#define SPAD 20   // smem row stride in words (conflict-free fragment loads)

__global__ __launch_bounds__(256) void mma_gemm_kernel(
    const float* __restrict__ A, const float* __restrict__ Bt,
    float* __restrict__ C, int Np)
{
    __shared__ uint32_t As[2][128][SPAD];
    __shared__ uint32_t Bs[2][128][SPAD];

    int tid  = threadIdx.x;
    int wid  = tid >> 5, lane = tid & 31;
    int gid  = lane >> 2, tig = lane & 3;
    int wm   = (wid & 1) * 64;     // warp row offset
    int wn   = (wid >> 1) * 32;    // warp col offset

    int lrow = tid >> 1;           // 0..127
    int lcol = (tid & 1) * 8;      // 0 or 8

    const float* Ab = A  + (size_t)blockIdx.y * 128 * GK + (size_t)lrow * GK + lcol;
    const float* Bb = Bt + (size_t)blockIdx.x * 128 * GK + (size_t)lrow * GK + lcol;

    float acc[4][4][4];
#pragma unroll
    for (int i = 0; i < 4; i++)
#pragma unroll
        for (int j = 0; j < 4; j++)
#pragma unroll
            for (int r = 0; r < 4; r++) acc[i][j][r] = 0.f;

    // preload chunk 0
    float4 ra0 = *(const float4*)(Ab);
    float4 ra1 = *(const float4*)(Ab + 4);
    float4 rb0 = *(const float4*)(Bb);
    float4 rb1 = *(const float4*)(Bb + 4);

    {   // store chunk 0 into buf 0 (tf32-rounded)
        uint32_t* pa = &As[0][lrow][lcol];
        uint32_t* pb = &Bs[0][lrow][lcol];
        pa[0]=f2tf32(ra0.x); pa[1]=f2tf32(ra0.y); pa[2]=f2tf32(ra0.z); pa[3]=f2tf32(ra0.w);
        pa[4]=f2tf32(ra1.x); pa[5]=f2tf32(ra1.y); pa[6]=f2tf32(ra1.z); pa[7]=f2tf32(ra1.w);
        pb[0]=f2tf32(rb0.x); pb[1]=f2tf32(rb0.y); pb[2]=f2tf32(rb0.z); pb[3]=f2tf32(rb0.w);
        pb[4]=f2tf32(rb1.x); pb[5]=f2tf32(rb1.y); pb[6]=f2tf32(rb1.z); pb[7]=f2tf32(rb1.w);
    }
    __syncthreads();

    const int NIT = GK / BKQ;      // 64
    for (int c = 0; c < NIT; c++) {
        int buf = c & 1;
        if (c + 1 < NIT) {         // prefetch next chunk to registers
            const float* An = Ab + (c + 1) * BKQ;
            const float* Bn = Bb + (c + 1) * BKQ;
            ra0 = *(const float4*)(An);     ra1 = *(const float4*)(An + 4);
            rb0 = *(const float4*)(Bn);     rb1 = *(const float4*)(Bn + 4);
        }

#pragma unroll
        for (int kk = 0; kk < 2; kk++) {
            int kb = kk * 8;
            uint32_t af[4][4], bf[4][2];
#pragma unroll
            for (int mt = 0; mt < 4; mt++) {
                int r0 = wm + mt * 16 + gid;
                af[mt][0] = As[buf][r0    ][kb + tig];
                af[mt][1] = As[buf][r0 + 8][kb + tig];
                af[mt][2] = As[buf][r0    ][kb + tig + 4];
                af[mt][3] = As[buf][r0 + 8][kb + tig + 4];
            }
#pragma unroll
            for (int nt = 0; nt < 4; nt++) {
                int n0 = wn + nt * 8 + gid;
                bf[nt][0] = Bs[buf][n0][kb + tig];
                bf[nt][1] = Bs[buf][n0][kb + tig + 4];
            }
#pragma unroll
            for (int mt = 0; mt < 4; mt++)
#pragma unroll
                for (int nt = 0; nt < 4; nt++)
                    mma_tf32(acc[mt][nt][0], acc[mt][nt][1], acc[mt][nt][2], acc[mt][nt][3],
                             af[mt][0], af[mt][1], af[mt][2], af[mt][3],
                             bf[nt][0], bf[nt][1]);
        }

        if (c + 1 < NIT) {
            int nbuf = buf ^ 1;
            uint32_t* pa = &As[nbuf][lrow][lcol];
            uint32_t* pb = &Bs[nbuf][lrow][lcol];
            pa[0]=f2tf32(ra0.x); pa[1]=f2tf32(ra0.y); pa[2]=f2tf32(ra0.z); pa[3]=f2tf32(ra0.w);
            pa[4]=f2tf32(ra1.x); pa[5]=f2tf32(ra1.y); pa[6]=f2tf32(ra1.z); pa[7]=f2tf32(ra1.w);
            pb[0]=f2tf32(rb0.x); pb[1]=f2tf32(rb0.y); pb[2]=f2tf32(rb0.z); pb[3]=f2tf32(rb0.w);
            pb[4]=f2tf32(rb1.x); pb[5]=f2tf32(rb1.y); pb[6]=f2tf32(rb1.z); pb[7]=f2tf32(rb1.w);
            __syncthreads();
        }
    }

    // epilogue
    int baseRow = blockIdx.y * 128 + wm;
    int baseCol = blockIdx.x * 128 + wn;
#pragma unroll
    for (int mt = 0; mt < 4; mt++) {
#pragma unroll
        for (int nt = 0; nt < 4; nt++) {
            int row = baseRow + mt * 16 + gid;
            int col = baseCol + nt * 8 + tig * 2;
            *(float2*)(C + (size_t)row * Np + col)       = make_float2(acc[mt][nt][0], acc[mt][nt][1]);
            *(float2*)(C + (size_t)(row + 8) * Np + col) = make_float2(acc[mt][nt][2], acc[mt][nt][3]);
        }
    }
}

// ---------------- pack: RMSNorm + RoPE (+gain) + layout transpose ----------
__global__ __launch_bounds__(256) void pack_kernel()
{
    int w    = (blockIdx.x * 256 + threadIdx.x) >> 5;
    int lane = threadIdx.x & 31;
    int t    = w / 24;
    int slot = w - t * 24;
    int b = t / SEQ;
    int n = t - b * SEQ;

    float v0, v1;
    float* dst;
    bool dorope;
    float gain = 1.0f;

    if (slot < 16) {
        const float* src = g_qp + (size_t)t * CDIM + slot * HD;
        v0 = src[lane]; v1 = src[lane + 32];
        dst = g_q + (((size_t)(b * NH + slot)) * SEQ + n) * HD;
        dorope = true; gain = 1.5f;
    } else if (slot < 20) {
        int h = slot - 16;
        const float* src = g_kp + (size_t)t * (NHKV*HD) + h * HD;
        v0 = src[lane]; v1 = src[lane + 32];
        dst = g_k + (((size_t)(b * NHKV + h)) * SEQ + n) * HD;
        dorope = true;
    } else {
        int h = slot - 20;
        const float* src = g_vp + (size_t)t * (NHKV*HD) + h * HD;
        v0 = src[lane]; v1 = src[lane + 32];
        dst = g_v + (((size_t)(b * NHKV + h)) * SEQ + n) * HD;
        dorope = false;
    }

    if (dorope) {
        float ss = v0*v0 + v1*v1;
#pragma unroll
        for (int o = 16; o; o >>= 1) ss += __shfl_xor_sync(0xffffffffu, ss, o);
        float r = rsqrtf(ss * (1.0f/64.0f) + 1.1920929e-7f);
        v0 *= r; v1 *= r;
        float inv_freq = powf(10000.0f, -(float)lane * (1.0f/32.0f));
        float ang = (float)n * inv_freq;
        float sv, cv;
        sincosf(ang, &sv, &cv);
        float o0 = v0*cv - v1*sv;
        float o1 = v1*cv + v0*sv;
        v0 = o0 * gain; v1 = o1 * gain;
    }
    dst[lane] = v0;
    dst[lane + 32] = v1;
}

// ---------------- causal flash attention (SIMT fp32) ------------------------
#define QTILE 128
#define KTILE 64
#define CHUNK 32

__global__ __launch_bounds__(128) void attn_kernel()
{
    __shared__ float Ks[KTILE*HD];
    __shared__ float Vs[KTILE*HD];

    int qt = blockIdx.x, h = blockIdx.y, b = blockIdx.z;
    int r = threadIdx.x;
    int qrow = qt * QTILE + r;
    int hkv = h >> 2;

    const float* qptr  = g_q + (((size_t)(b*NH   + h  )) * SEQ + qrow) * HD;
    const float* kbase = g_k +  ((size_t)(b*NHKV + hkv)) * SEQ * HD;
    const float* vbase = g_v +  ((size_t)(b*NHKV + hkv)) * SEQ * HD;

    float q[HD];
#pragma unroll
    for (int d = 0; d < HD; d += 4) {
        float4 t4 = *(const float4*)(qptr + d);
        q[d] = t4.x; q[d+1] = t4.y; q[d+2] = t4.z; q[d+3] = t4.w;
    }

    float acc[HD];
#pragma unroll
    for (int d = 0; d < HD; d++) acc[d] = 0.f;
    float m = -1e30f, l = 0.f;

    int ntiles = (qt + 1) * (QTILE / KTILE);
    for (int kt = 0; kt < ntiles; kt++) {
        int k0 = kt * KTILE;
        __syncthreads();
#pragma unroll
        for (int i = 0; i < (KTILE*HD)/(128*4); i++) {
            int idx = (i * 128 + r) * 4;
            *(float4*)&Ks[idx] = *(const float4*)&kbase[(size_t)k0 * HD + idx];
            *(float4*)&Vs[idx] = *(const float4*)&vbase[(size_t)k0 * HD + idx];
        }
        __syncthreads();

#pragma unroll
        for (int ch = 0; ch < KTILE/CHUNK; ch++) {
            int base = k0 + ch * CHUNK;
            if (base > qrow) continue;

            float s[CHUNK];
#pragma unroll
            for (int j = 0; j < CHUNK; j++) {
                const float4* kp = (const float4*)&Ks[(ch*CHUNK + j) * HD];
                float s0=0.f, s1=0.f, s2=0.f, s3=0.f;
#pragma unroll
                for (int d4 = 0; d4 < HD/4; d4++) {
                    float4 kv = kp[d4];
                    s0 += q[d4*4+0] * kv.x;
                    s1 += q[d4*4+1] * kv.y;
                    s2 += q[d4*4+2] * kv.z;
                    s3 += q[d4*4+3] * kv.w;
                }
                s[j] = (s0 + s1) + (s2 + s3);
            }

            float mloc = m;
#pragma unroll
            for (int j = 0; j < CHUNK; j++) {
                s[j] = (base + j <= qrow) ? s[j] * 0.125f : -1e30f;
                mloc = fmaxf(mloc, s[j]);
            }
            float corr = __expf(m - mloc);
            m = mloc;
            l *= corr;
#pragma unroll
            for (int d = 0; d < HD; d++) acc[d] *= corr;

#pragma unroll
            for (int j = 0; j < CHUNK; j++) {
                float p = __expf(s[j] - mloc);
                l += p;
                const float4* vp4 = (const float4*)&Vs[(ch*CHUNK + j) * HD];
#pragma unroll
                for (int d4 = 0; d4 < HD/4; d4++) {
                    float4 vv = vp4[d4];
                    acc[d4*4+0] += p * vv.x;
                    acc[d4*4+1] += p * vv.y;
                    acc[d4*4+2] += p * vv.z;
                    acc[d4*4+3] += p * vv.w;
                }
            }
        }
    }

    float invl = 1.0f / l;
    float* y = g_y + (((size_t)(b*SEQ + qrow)) * NH + h) * HD;
#pragma unroll
    for (int d4 = 0; d4 < HD/4; d4++) {
        float4 o;
        o.x = acc[d4*4+0] * invl;
        o.y = acc[d4*4+1] * invl;
        o.z = acc[d4*4+2] * invl;
        o.w = acc[d4*4+3] * invl;
        ((float4*)y)[d4] = o;
    }
}

// ---------------- launch ----------------------------------------------------
extern "C" void kernel_launch(void* const* d_in, const int* in_sizes, int n_in,
                              void* d_out, int out_size)
{
    const float* x  = (const float*)d_in[0];
    const float* wq = (const float*)d_in[1];
    const float* wk = (const float*)d_in[2];
    const float* wv = (const float*)d_in[3];
    const float* wo = (const float*)d_in[4];
    float* out = (float*)d_out;

    float *qp, *kp, *vp, *yy, *wqT, *wkT, *wvT, *woT;
    cudaGetSymbolAddress((void**)&qp,  g_qp);
    cudaGetSymbolAddress((void**)&kp,  g_kp);
    cudaGetSymbolAddress((void**)&vp,  g_vp);
    cudaGetSymbolAddress((void**)&yy,  g_y);
    cudaGetSymbolAddress((void**)&wqT, g_wqT);
    cudaGetSymbolAddress((void**)&wkT, g_wkT);
    cudaGetSymbolAddress((void**)&wvT, g_wvT);
    cudaGetSymbolAddress((void**)&woT, g_woT);

    // weight transposes -> [N,K]
    transpose_kernel<<<dim3(32,32), dim3(32,8)>>>(wq, wqT, CDIM, CDIM);
    transpose_kernel<<<dim3(8, 32), dim3(32,8)>>>(wk, wkT, CDIM, NHKV*HD);
    transpose_kernel<<<dim3(8, 32), dim3(32,8)>>>(wv, wvT, CDIM, NHKV*HD);
    transpose_kernel<<<dim3(32,32), dim3(32,8)>>>(wo, woT, CDIM, CDIM);

    // QKV projections (tf32 tensor cores via mma.sync)
    mma_gemm_kernel<<<dim3(CDIM/128, TOK/128), 256>>>(x, wqT, qp, CDIM);
    mma_gemm_kernel<<<dim3((NHKV*HD)/128, TOK/128), 256>>>(x, wkT, kp, NHKV*HD);
    mma_gemm_kernel<<<dim3((NHKV*HD)/128, TOK/128), 256>>>(x, wvT, vp, NHKV*HD);

    // RMSNorm + RoPE + transpose
    pack_kernel<<<(TOK*24)/8, 256>>>();

    // causal SDPA
    dim3 ga(SEQ/QTILE, NH, BATCH);
    attn_kernel<<<ga, 128>>>();

    // output projection
    mma_gemm_kernel<<<dim3(CDIM/128, TOK/128), 256>>>(yy, woT, out, CDIM);
}

// round 4
// speedup vs baseline: 3.2853x; 2.7548x over previous
#include <cuda_runtime.h>
#include <math.h>
#include <stdint.h>

// ---------------- problem constants ----------------
#define BATCH 4
#define SEQ   2048
#define CDIM  1024
#define NH    16
#define NHKV  4
#define HD    64
#define TOK   (BATCH*SEQ)          // 8192
#define GK    1024                 // K dim of every GEMM

// ---------------- scratch (device globals; no allocation allowed) ----------
__device__ float g_qp[TOK*CDIM];
__device__ float g_kp[TOK*NHKV*HD];
__device__ float g_vp[TOK*NHKV*HD];
__device__ float g_q [BATCH*NH*SEQ*HD];
__device__ float g_k [BATCH*NHKV*SEQ*HD];
__device__ float g_v [BATCH*NHKV*SEQ*HD];
__device__ float g_y [TOK*CDIM];
__device__ float g_wqT[CDIM*CDIM];         // [N,K] transposed weights
__device__ float g_wkT[NHKV*HD*CDIM];
__device__ float g_wvT[NHKV*HD*CDIM];
__device__ float g_woT[CDIM*CDIM];

// ---------------- helpers ----------------
__device__ __forceinline__ uint32_t f2tf32(float f) {
    uint32_t r;
    asm("cvt.rna.tf32.f32 %0, %1;" : "=r"(r) : "f"(f));
    return r;
}
__device__ __forceinline__ void mma_tf32(float& d0, float& d1, float& d2, float& d3,
                                         uint32_t a0, uint32_t a1, uint32_t a2, uint32_t a3,
                                         uint32_t b0, uint32_t b1) {
    asm volatile(
        "mma.sync.aligned.m16n8k8.row.col.f32.tf32.tf32.f32 "
        "{%0,%1,%2,%3}, {%4,%5,%6,%7}, {%8,%9}, {%0,%1,%2,%3};"
        : "+f"(d0), "+f"(d1), "+f"(d2), "+f"(d3)
        : "r"(a0), "r"(a1), "r"(a2), "r"(a3), "r"(b0), "r"(b1));
}

// ---------------- weight transpose: D[c][r] = S[r][c] ----------------------
__global__ __launch_bounds__(256) void transpose_kernel(
    const float* __restrict__ S, float* __restrict__ D, int R, int Ccols)
{
    __shared__ float t[32][33];
    int bx = blockIdx.x * 32, by = blockIdx.y * 32;
#pragma unroll
    for (int i = 0; i < 32; i += 8)
        t[threadIdx.y + i][threadIdx.x] = S[(size_t)(by + threadIdx.y + i) * Ccols + bx + threadIdx.x];
    __syncthreads();
#pragma unroll
    for (int i = 0; i < 32; i += 8)
        D[(size_t)(bx + threadIdx.y + i) * R + by + threadIdx.x] = t[threadIdx.x][threadIdx.y + i];
}

// ---------------- tf32 mma.sync GEMM: C[M,Np] = A[M,1024] @ Bt[Np,1024]^T ---
#define BKQ 16
#define SPAD 20

__global__ __launch_bounds__(256) void mma_gemm_kernel(
    const float* __restrict__ A, const float* __restrict__ Bt,
    float* __restrict__ C, int Np)
{
    __shared__ uint32_t As[2][128][SPAD];
    __shared__ uint32_t Bs[2][128][SPAD];

    int tid  = threadIdx.x;
    int wid  = tid >> 5, lane = tid & 31;
    int gid  = lane >> 2, tig = lane & 3;
    int wm   = (wid & 1) * 64;
    int wn   = (wid >> 1) * 32;

    int lrow = tid >> 1;
    int lcol = (tid & 1) * 8;

    const float* Ab = A  + (size_t)blockIdx.y * 128 * GK + (size_t)lrow * GK + lcol;
    const float* Bb = Bt + (size_t)blockIdx.x * 128 * GK + (size_t)lrow * GK + lcol;

    float acc[4][4][4];
#pragma unroll
    for (int i = 0; i < 4; i++)
#pragma unroll
        for (int j = 0; j < 4; j++)
#pragma unroll
            for (int r = 0; r < 4; r++) acc[i][j][r] = 0.f;

    float4 ra0 = *(const float4*)(Ab);
    float4 ra1 = *(const float4*)(Ab + 4);
    float4 rb0 = *(const float4*)(Bb);
    float4 rb1 = *(const float4*)(Bb + 4);

    {
        uint32_t* pa = &As[0][lrow][lcol];
        uint32_t* pb = &Bs[0][lrow][lcol];
        pa[0]=f2tf32(ra0.x); pa[1]=f2tf32(ra0.y); pa[2]=f2tf32(ra0.z); pa[3]=f2tf32(ra0.w);
        pa[4]=f2tf32(ra1.x); pa[5]=f2tf32(ra1.y); pa[6]=f2tf32(ra1.z); pa[7]=f2tf32(ra1.w);
        pb[0]=f2tf32(rb0.x); pb[1]=f2tf32(rb0.y); pb[2]=f2tf32(rb0.z); pb[3]=f2tf32(rb0.w);
        pb[4]=f2tf32(rb1.x); pb[5]=f2tf32(rb1.y); pb[6]=f2tf32(rb1.z); pb[7]=f2tf32(rb1.w);
    }
    __syncthreads();

    const int NIT = GK / BKQ;
    for (int c = 0; c < NIT; c++) {
        int buf = c & 1;
        if (c + 1 < NIT) {
            const float* An = Ab + (c + 1) * BKQ;
            const float* Bn = Bb + (c + 1) * BKQ;
            ra0 = *(const float4*)(An);     ra1 = *(const float4*)(An + 4);
            rb0 = *(const float4*)(Bn);     rb1 = *(const float4*)(Bn + 4);
        }

#pragma unroll
        for (int kk = 0; kk < 2; kk++) {
            int kb = kk * 8;
            uint32_t af[4][4], bf[4][2];
#pragma unroll
            for (int mt = 0; mt < 4; mt++) {
                int r0 = wm + mt * 16 + gid;
                af[mt][0] = As[buf][r0    ][kb + tig];
                af[mt][1] = As[buf][r0 + 8][kb + tig];
                af[mt][2] = As[buf][r0    ][kb + tig + 4];
                af[mt][3] = As[buf][r0 + 8][kb + tig + 4];
            }
#pragma unroll
            for (int nt = 0; nt < 4; nt++) {
                int n0 = wn + nt * 8 + gid;
                bf[nt][0] = Bs[buf][n0][kb + tig];
                bf[nt][1] = Bs[buf][n0][kb + tig + 4];
            }
#pragma unroll
            for (int mt = 0; mt < 4; mt++)
#pragma unroll
                for (int nt = 0; nt < 4; nt++)
                    mma_tf32(acc[mt][nt][0], acc[mt][nt][1], acc[mt][nt][2], acc[mt][nt][3],
                             af[mt][0], af[mt][1], af[mt][2], af[mt][3],
                             bf[nt][0], bf[nt][1]);
        }

        if (c + 1 < NIT) {
            int nbuf = buf ^ 1;
            uint32_t* pa = &As[nbuf][lrow][lcol];
            uint32_t* pb = &Bs[nbuf][lrow][lcol];
            pa[0]=f2tf32(ra0.x); pa[1]=f2tf32(ra0.y); pa[2]=f2tf32(ra0.z); pa[3]=f2tf32(ra0.w);
            pa[4]=f2tf32(ra1.x); pa[5]=f2tf32(ra1.y); pa[6]=f2tf32(ra1.z); pa[7]=f2tf32(ra1.w);
            pb[0]=f2tf32(rb0.x); pb[1]=f2tf32(rb0.y); pb[2]=f2tf32(rb0.z); pb[3]=f2tf32(rb0.w);
            pb[4]=f2tf32(rb1.x); pb[5]=f2tf32(rb1.y); pb[6]=f2tf32(rb1.z); pb[7]=f2tf32(rb1.w);
            __syncthreads();
        }
    }

    int baseRow = blockIdx.y * 128 + wm;
    int baseCol = blockIdx.x * 128 + wn;
#pragma unroll
    for (int mt = 0; mt < 4; mt++) {
#pragma unroll
        for (int nt = 0; nt < 4; nt++) {
            int row = baseRow + mt * 16 + gid;
            int col = baseCol + nt * 8 + tig * 2;
            *(float2*)(C + (size_t)row * Np + col)       = make_float2(acc[mt][nt][0], acc[mt][nt][1]);
            *(float2*)(C + (size_t)(row + 8) * Np + col) = make_float2(acc[mt][nt][2], acc[mt][nt][3]);
        }
    }
}

// ---------------- pack: RMSNorm + RoPE (+gain) + layout transpose ----------
__global__ __launch_bounds__(256) void pack_kernel()
{
    int w    = (blockIdx.x * 256 + threadIdx.x) >> 5;
    int lane = threadIdx.x & 31;
    int t    = w / 24;
    int slot = w - t * 24;
    int b = t / SEQ;
    int n = t - b * SEQ;

    float v0, v1;
    float* dst;
    bool dorope;
    float gain = 1.0f;

    if (slot < 16) {
        const float* src = g_qp + (size_t)t * CDIM + slot * HD;
        v0 = src[lane]; v1 = src[lane + 32];
        dst = g_q + (((size_t)(b * NH + slot)) * SEQ + n) * HD;
        dorope = true; gain = 1.5f;
    } else if (slot < 20) {
        int h = slot - 16;
        const float* src = g_kp + (size_t)t * (NHKV*HD) + h * HD;
        v0 = src[lane]; v1 = src[lane + 32];
        dst = g_k + (((size_t)(b * NHKV + h)) * SEQ + n) * HD;
        dorope = true;
    } else {
        int h = slot - 20;
        const float* src = g_vp + (size_t)t * (NHKV*HD) + h * HD;
        v0 = src[lane]; v1 = src[lane + 32];
        dst = g_v + (((size_t)(b * NHKV + h)) * SEQ + n) * HD;
        dorope = false;
    }

    if (dorope) {
        float ss = v0*v0 + v1*v1;
#pragma unroll
        for (int o = 16; o; o >>= 1) ss += __shfl_xor_sync(0xffffffffu, ss, o);
        float r = rsqrtf(ss * (1.0f/64.0f) + 1.1920929e-7f);
        v0 *= r; v1 *= r;
        float inv_freq = powf(10000.0f, -(float)lane * (1.0f/32.0f));
        float ang = (float)n * inv_freq;
        float sv, cv;
        sincosf(ang, &sv, &cv);
        float o0 = v0*cv - v1*sv;
        float o1 = v1*cv + v0*sv;
        v0 = o0 * gain; v1 = o1 * gain;
    }
    dst[lane] = v0;
    dst[lane + 32] = v1;
}

// ---------------- tensor-core causal flash attention (tf32 mma.sync) -------
// CTA: 64 q-rows for one (b,h); 4 warps x 16 rows. K-tiles of 64 keys.
// smem (dynamic): Ks[64][68] (key-major), Vs[64][68] (dim-major), Ps[64][68]
#define APAD 68
#define AKS(k,d) smA[(k)*APAD + (d)]
#define AVS(d,k) smA[64*APAD + (d)*APAD + (k)]
#define APS(r,c) smA[2*64*APAD + (r)*APAD + (c)]
#define ATTN_SMEM (3*64*APAD*4)

__global__ __launch_bounds__(128) void attn_mma_kernel()
{
    extern __shared__ uint32_t smA[];

    int qb = blockIdx.x, h = blockIdx.y, b = blockIdx.z;
    int tid = threadIdx.x;
    int wid = tid >> 5, lane = tid & 31;
    int gid = lane >> 2, tig = lane & 3;
    int r0 = wid * 16;
    int hkv = h >> 2;

    const float* qbase = g_q + ((size_t)(b*NH   + h  )) * SEQ * HD;
    const float* kbase = g_k + ((size_t)(b*NHKV + hkv)) * SEQ * HD;
    const float* vbase = g_v + ((size_t)(b*NHKV + hkv)) * SEQ * HD;

    int skey  = tid & 63;       // staging row
    int shalf = tid >> 6;       // dim half

    // ---- stage Q (scaled by 1/8) into Ps, then fragment-load to registers
    {
        const float* qr = qbase + (size_t)(qb*64 + skey) * HD + shalf*32;
#pragma unroll
        for (int i = 0; i < 8; i++) {
            float4 f = *(const float4*)(qr + i*4);
            int d = shalf*32 + i*4;
            APS(skey, d+0) = f2tf32(f.x * 0.125f);
            APS(skey, d+1) = f2tf32(f.y * 0.125f);
            APS(skey, d+2) = f2tf32(f.z * 0.125f);
            APS(skey, d+3) = f2tf32(f.w * 0.125f);
        }
    }
    __syncthreads();

    uint32_t qf[8][4];
#pragma unroll
    for (int ks = 0; ks < 8; ks++) {
        qf[ks][0] = APS(r0+gid,     ks*8+tig);
        qf[ks][1] = APS(r0+gid+8,   ks*8+tig);
        qf[ks][2] = APS(r0+gid,     ks*8+tig+4);
        qf[ks][3] = APS(r0+gid+8,   ks*8+tig+4);
    }

    float m0 = -1e30f, m1 = -1e30f, l0 = 0.f, l1 = 0.f;
    float o[8][4];
#pragma unroll
    for (int nt = 0; nt < 8; nt++)
#pragma unroll
        for (int j = 0; j < 4; j++) o[nt][j] = 0.f;

    int row0 = qb*64 + r0 + gid;        // global q row for c0/c1
    int row1 = row0 + 8;                // for c2/c3

    for (int kt = 0; kt <= qb; kt++) {
        int k0 = kt * 64;
        __syncthreads();
        // ---- stage K (key-major) and V (dim-major, transposed)
        {
            const float* kr = kbase + (size_t)(k0 + skey) * HD + shalf*32;
            const float* vr = vbase + (size_t)(k0 + skey) * HD + shalf*32;
#pragma unroll
            for (int i = 0; i < 8; i++) {
                float4 f = *(const float4*)(kr + i*4);
                float4 g = *(const float4*)(vr + i*4);
                int d = shalf*32 + i*4;
                AKS(skey, d+0) = f2tf32(f.x);
                AKS(skey, d+1) = f2tf32(f.y);
                AKS(skey, d+2) = f2tf32(f.z);
                AKS(skey, d+3) = f2tf32(f.w);
                AVS(d+0, skey) = f2tf32(g.x);
                AVS(d+1, skey) = f2tf32(g.y);
                AVS(d+2, skey) = f2tf32(g.z);
                AVS(d+3, skey) = f2tf32(g.w);
            }
        }
        __syncthreads();

        // ---- scores S = Q @ K^T (already scaled)
        float s[8][4];
#pragma unroll
        for (int nt = 0; nt < 8; nt++)
#pragma unroll
            for (int j = 0; j < 4; j++) s[nt][j] = 0.f;

#pragma unroll
        for (int ks = 0; ks < 8; ks++) {
#pragma unroll
            for (int nt = 0; nt < 8; nt++) {
                uint32_t b0 = AKS(nt*8+gid, ks*8+tig);
                uint32_t b1 = AKS(nt*8+gid, ks*8+tig+4);
                mma_tf32(s[nt][0], s[nt][1], s[nt][2], s[nt][3],
                         qf[ks][0], qf[ks][1], qf[ks][2], qf[ks][3], b0, b1);
            }
        }

        // ---- causal mask (diagonal tile only)
        if (kt == qb) {
#pragma unroll
            for (int nt = 0; nt < 8; nt++) {
                int key = k0 + nt*8 + 2*tig;
                if (key     > row0) s[nt][0] = -1e30f;
                if (key + 1 > row0) s[nt][1] = -1e30f;
                if (key     > row1) s[nt][2] = -1e30f;
                if (key + 1 > row1) s[nt][3] = -1e30f;
            }
        }

        // ---- online softmax
        float mx0 = m0, mx1 = m1;
#pragma unroll
        for (int nt = 0; nt < 8; nt++) {
            mx0 = fmaxf(mx0, fmaxf(s[nt][0], s[nt][1]));
            mx1 = fmaxf(mx1, fmaxf(s[nt][2], s[nt][3]));
        }
        mx0 = fmaxf(mx0, __shfl_xor_sync(0xffffffffu, mx0, 1));
        mx0 = fmaxf(mx0, __shfl_xor_sync(0xffffffffu, mx0, 2));
        mx1 = fmaxf(mx1, __shfl_xor_sync(0xffffffffu, mx1, 1));
        mx1 = fmaxf(mx1, __shfl_xor_sync(0xffffffffu, mx1, 2));

        float c0 = __expf(m0 - mx0);
        float c1 = __expf(m1 - mx1);
        m0 = mx0; m1 = mx1;
        l0 *= c0;  l1 *= c1;
#pragma unroll
        for (int nt = 0; nt < 8; nt++) {
            o[nt][0] *= c0; o[nt][1] *= c0;
            o[nt][2] *= c1; o[nt][3] *= c1;
        }

        float ps0 = 0.f, ps1 = 0.f;
#pragma unroll
        for (int nt = 0; nt < 8; nt++) {
            s[nt][0] = __expf(s[nt][0] - mx0);
            s[nt][1] = __expf(s[nt][1] - mx0);
            s[nt][2] = __expf(s[nt][2] - mx1);
            s[nt][3] = __expf(s[nt][3] - mx1);
            ps0 += s[nt][0] + s[nt][1];
            ps1 += s[nt][2] + s[nt][3];
        }
        ps0 += __shfl_xor_sync(0xffffffffu, ps0, 1);
        ps0 += __shfl_xor_sync(0xffffffffu, ps0, 2);
        ps1 += __shfl_xor_sync(0xffffffffu, ps1, 1);
        ps1 += __shfl_xor_sync(0xffffffffu, ps1, 2);
        l0 += ps0; l1 += ps1;

        // ---- P -> smem (warp-private rows)
#pragma unroll
        for (int nt = 0; nt < 8; nt++) {
            int c = nt*8 + 2*tig;
            APS(r0+gid,   c  ) = f2tf32(s[nt][0]);
            APS(r0+gid,   c+1) = f2tf32(s[nt][1]);
            APS(r0+gid+8, c  ) = f2tf32(s[nt][2]);
            APS(r0+gid+8, c+1) = f2tf32(s[nt][3]);
        }
        __syncwarp();

        // ---- O += P @ V
#pragma unroll
        for (int ks = 0; ks < 8; ks++) {
            uint32_t a0 = APS(r0+gid,   ks*8+tig);
            uint32_t a1 = APS(r0+gid+8, ks*8+tig);
            uint32_t a2 = APS(r0+gid,   ks*8+tig+4);
            uint32_t a3 = APS(r0+gid+8, ks*8+tig+4);
#pragma unroll
            for (int nt = 0; nt < 8; nt++) {
                uint32_t b0 = AVS(nt*8+gid, ks*8+tig);
                uint32_t b1 = AVS(nt*8+gid, ks*8+tig+4);
                mma_tf32(o[nt][0], o[nt][1], o[nt][2], o[nt][3],
                         a0, a1, a2, a3, b0, b1);
            }
        }
    }

    // ---- finalize: divide by l, write to g_y[b][n][h][d]
    float i0 = 1.0f / l0, i1 = 1.0f / l1;
    float* y0 = g_y + (((size_t)(b*SEQ + row0)) * NH + h) * HD;
    float* y1 = g_y + (((size_t)(b*SEQ + row1)) * NH + h) * HD;
#pragma unroll
    for (int nt = 0; nt < 8; nt++) {
        int c = nt*8 + 2*tig;
        *(float2*)(y0 + c) = make_float2(o[nt][0] * i0, o[nt][1] * i0);
        *(float2*)(y1 + c) = make_float2(o[nt][2] * i1, o[nt][3] * i1);
    }
}

// ---------------- launch ----------------------------------------------------
extern "C" void kernel_launch(void* const* d_in, const int* in_sizes, int n_in,
                              void* d_out, int out_size)
{
    const float* x  = (const float*)d_in[0];
    const float* wq = (const float*)d_in[1];
    const float* wk = (const float*)d_in[2];
    const float* wv = (const float*)d_in[3];
    const float* wo = (const float*)d_in[4];
    float* out = (float*)d_out;

    float *qp, *kp, *vp, *yy, *wqT, *wkT, *wvT, *woT;
    cudaGetSymbolAddress((void**)&qp,  g_qp);
    cudaGetSymbolAddress((void**)&kp,  g_kp);
    cudaGetSymbolAddress((void**)&vp,  g_vp);
    cudaGetSymbolAddress((void**)&yy,  g_y);
    cudaGetSymbolAddress((void**)&wqT, g_wqT);
    cudaGetSymbolAddress((void**)&wkT, g_wkT);
    cudaGetSymbolAddress((void**)&wvT, g_wvT);
    cudaGetSymbolAddress((void**)&woT, g_woT);

    cudaFuncSetAttribute(attn_mma_kernel, cudaFuncAttributeMaxDynamicSharedMemorySize, ATTN_SMEM);

    // weight transposes -> [N,K]
    transpose_kernel<<<dim3(32,32), dim3(32,8)>>>(wq, wqT, CDIM, CDIM);
    transpose_kernel<<<dim3(8, 32), dim3(32,8)>>>(wk, wkT, CDIM, NHKV*HD);
    transpose_kernel<<<dim3(8, 32), dim3(32,8)>>>(wv, wvT, CDIM, NHKV*HD);
    transpose_kernel<<<dim3(32,32), dim3(32,8)>>>(wo, woT, CDIM, CDIM);

    // QKV projections (tf32 tensor cores via mma.sync)
    mma_gemm_kernel<<<dim3(CDIM/128, TOK/128), 256>>>(x, wqT, qp, CDIM);
    mma_gemm_kernel<<<dim3((NHKV*HD)/128, TOK/128), 256>>>(x, wkT, kp, NHKV*HD);
    mma_gemm_kernel<<<dim3((NHKV*HD)/128, TOK/128), 256>>>(x, wvT, vp, NHKV*HD);

    // RMSNorm + RoPE + transpose
    pack_kernel<<<(TOK*24)/8, 256>>>();

    // causal SDPA (tensor cores)
    attn_mma_kernel<<<dim3(SEQ/64, NH, BATCH), 128, ATTN_SMEM>>>();

    // output projection
    mma_gemm_kernel<<<dim3(CDIM/128, TOK/128), 256>>>(yy, woT, out, CDIM);
}

// round 5
// speedup vs baseline: 3.3590x; 1.0224x over previous
#include <cuda_runtime.h>
#include <math.h>
#include <stdint.h>

// ---------------- problem constants ----------------
#define BATCH 4
#define SEQ   2048
#define CDIM  1024
#define NH    16
#define NHKV  4
#define HD    64
#define TOK   (BATCH*SEQ)          // 8192
#define GK    1024                 // K dim of every GEMM
#define NQKV  1536                 // 1024 + 256 + 256

// ---------------- scratch (device globals; no allocation allowed) ----------
__device__ uint32_t g_xc  [TOK*CDIM];        // x as tf32 bits
__device__ float    g_qkv [TOK*NQKV];        // fused qkv projection (fp32)
__device__ float    g_q [BATCH*NH*SEQ*HD];
__device__ float    g_k [BATCH*NHKV*SEQ*HD];
__device__ float    g_v [BATCH*NHKV*SEQ*HD];
__device__ uint32_t g_y [TOK*CDIM];          // attention out as tf32 bits
__device__ uint32_t g_wqkvT[NQKV*CDIM];      // [N,K] transposed weights, tf32 bits
__device__ uint32_t g_woT  [CDIM*CDIM];

// ---------------- helpers ----------------
__device__ __forceinline__ uint32_t f2tf32(float f) {
    uint32_t r;
    asm("cvt.rna.tf32.f32 %0, %1;" : "=r"(r) : "f"(f));
    return r;
}
__device__ __forceinline__ uint32_t smem_u32(const void* p) {
    uint32_t a;
    asm("{ .reg .u64 t; cvta.to.shared.u64 t, %1; cvt.u32.u64 %0, t; }" : "=r"(a) : "l"(p));
    return a;
}
__device__ __forceinline__ void mma_tf32(float& d0, float& d1, float& d2, float& d3,
                                         uint32_t a0, uint32_t a1, uint32_t a2, uint32_t a3,
                                         uint32_t b0, uint32_t b1) {
    asm volatile(
        "mma.sync.aligned.m16n8k8.row.col.f32.tf32.tf32.f32 "
        "{%0,%1,%2,%3}, {%4,%5,%6,%7}, {%8,%9}, {%0,%1,%2,%3};"
        : "+f"(d0), "+f"(d1), "+f"(d2), "+f"(d3)
        : "r"(a0), "r"(a1), "r"(a2), "r"(a3), "r"(b0), "r"(b1));
}
#define CP_ASYNC16(saddr, gptr) \
    asm volatile("cp.async.cg.shared.global [%0], [%1], 16;" :: "r"(saddr), "l"(gptr))
#define CP_COMMIT()  asm volatile("cp.async.commit_group;" ::: "memory")
#define CP_WAIT(n)   asm volatile("cp.async.wait_group %0;" :: "n"(n) : "memory")

// ---------------- x -> tf32 bits -------------------------------------------
__global__ __launch_bounds__(256) void xconv_kernel(const float* __restrict__ x)
{
    int i = (blockIdx.x * 256 + threadIdx.x) * 4;
    float4 f = *(const float4*)(x + i);
    uint4 u;
    u.x = f2tf32(f.x); u.y = f2tf32(f.y); u.z = f2tf32(f.z); u.w = f2tf32(f.w);
    *(uint4*)(g_xc + i) = u;
}

// ---------------- weight transpose (+tf32): D[c][r] = tf32(S[r][c]) --------
__global__ __launch_bounds__(256) void transpose_kernel(
    const float* __restrict__ S, uint32_t* __restrict__ D, int R, int Ccols)
{
    __shared__ float t[32][33];
    int bx = blockIdx.x * 32, by = blockIdx.y * 32;
#pragma unroll
    for (int i = 0; i < 32; i += 8)
        t[threadIdx.y + i][threadIdx.x] = S[(size_t)(by + threadIdx.y + i) * Ccols + bx + threadIdx.x];
    __syncthreads();
#pragma unroll
    for (int i = 0; i < 32; i += 8)
        D[(size_t)(bx + threadIdx.y + i) * R + by + threadIdx.x] = f2tf32(t[threadIdx.x][threadIdx.y + i]);
}

// ---------------- tf32 GEMM, cp.async 3-stage pipeline ----------------------
// C[M,Np] = A[M,1024] @ Bt[Np,1024]^T.  A,Bt are tf32 bits. CTA 128x128x32.
// 256 thr, 8 warps (2x4), warp tile 64x32.
#define GS   3
#define GBK  32
#define GSTR 36                       // padded smem row stride (words)
#define STAGE_W (128*GSTR)            // words per stage
#define GEMM_SMEM (2*GS*STAGE_W*4)    // 110592 B

__global__ __launch_bounds__(256) void mma_gemm_kernel(
    const uint32_t* __restrict__ A, const uint32_t* __restrict__ Bt,
    float* __restrict__ C, int Np)
{
    extern __shared__ uint32_t gsm[];
    uint32_t* As = gsm;
    uint32_t* Bs = gsm + GS*STAGE_W;

    int tid  = threadIdx.x;
    int wid  = tid >> 5, lane = tid & 31;
    int gid  = lane >> 2, tig = lane & 3;
    int wm   = (wid & 1) * 64;
    int wn   = (wid >> 1) * 32;

    int lr = tid >> 1;            // row 0..127
    int lc = (tid & 1) * 16;      // word col base 0/16

    const uint32_t* Ag = A  + (size_t)blockIdx.y * 128 * GK + (size_t)lr * GK + lc;
    const uint32_t* Bg = Bt + (size_t)blockIdx.x * 128 * GK + (size_t)lr * GK + lc;

    uint32_t sA = smem_u32(As) + (uint32_t)(lr * GSTR + lc) * 4u;
    uint32_t sB = smem_u32(Bs) + (uint32_t)(lr * GSTR + lc) * 4u;
    const uint32_t stageB = STAGE_W * 4u;

    float acc[4][4][4];
#pragma unroll
    for (int i = 0; i < 4; i++)
#pragma unroll
        for (int j = 0; j < 4; j++)
#pragma unroll
            for (int r = 0; r < 4; r++) acc[i][j][r] = 0.f;

    const int NIT = GK / GBK;     // 32

    // prologue: stages 0..GS-2
#pragma unroll
    for (int s = 0; s < GS-1; s++) {
#pragma unroll
        for (int i = 0; i < 4; i++) {
            CP_ASYNC16(sA + s*stageB + i*16, Ag + s*GBK + i*4);
            CP_ASYNC16(sB + s*stageB + i*16, Bg + s*GBK + i*4);
        }
        CP_COMMIT();
    }

    for (int c = 0; c < NIT; c++) {
        CP_WAIT(GS-2);
        __syncthreads();

        int nc = c + GS - 1;
        if (nc < NIT) {
            int s = nc % GS;
#pragma unroll
            for (int i = 0; i < 4; i++) {
                CP_ASYNC16(sA + s*stageB + i*16, Ag + nc*GBK + i*4);
                CP_ASYNC16(sB + s*stageB + i*16, Bg + nc*GBK + i*4);
            }
            CP_COMMIT();
        }

        const uint32_t* Ab_ = As + (c % GS) * STAGE_W;
        const uint32_t* Bb_ = Bs + (c % GS) * STAGE_W;

#pragma unroll
        for (int kk = 0; kk < 4; kk++) {
            int kb = kk * 8;
            uint32_t af[4][4], bf[4][2];
#pragma unroll
            for (int mt = 0; mt < 4; mt++) {
                int r0 = (wm + mt*16 + gid) * GSTR;
                af[mt][0] = Ab_[r0            + kb + tig];
                af[mt][1] = Ab_[r0 + 8*GSTR   + kb + tig];
                af[mt][2] = Ab_[r0            + kb + tig + 4];
                af[mt][3] = Ab_[r0 + 8*GSTR   + kb + tig + 4];
            }
#pragma unroll
            for (int nt = 0; nt < 4; nt++) {
                int n0 = (wn + nt*8 + gid) * GSTR;
                bf[nt][0] = Bb_[n0 + kb + tig];
                bf[nt][1] = Bb_[n0 + kb + tig + 4];
            }
#pragma unroll
            for (int mt = 0; mt < 4; mt++)
#pragma unroll
                for (int nt = 0; nt < 4; nt++)
                    mma_tf32(acc[mt][nt][0], acc[mt][nt][1], acc[mt][nt][2], acc[mt][nt][3],
                             af[mt][0], af[mt][1], af[mt][2], af[mt][3],
                             bf[nt][0], bf[nt][1]);
        }
    }

    int baseRow = blockIdx.y * 128 + wm;
    int baseCol = blockIdx.x * 128 + wn;
#pragma unroll
    for (int mt = 0; mt < 4; mt++) {
#pragma unroll
        for (int nt = 0; nt < 4; nt++) {
            int row = baseRow + mt * 16 + gid;
            int col = baseCol + nt * 8 + tig * 2;
            *(float2*)(C + (size_t)row * Np + col)       = make_float2(acc[mt][nt][0], acc[mt][nt][1]);
            *(float2*)(C + (size_t)(row + 8) * Np + col) = make_float2(acc[mt][nt][2], acc[mt][nt][3]);
        }
    }
}

// ---------------- pack: RMSNorm + RoPE (+gain) + layout transpose ----------
__global__ __launch_bounds__(256) void pack_kernel()
{
    int w    = (blockIdx.x * 256 + threadIdx.x) >> 5;
    int lane = threadIdx.x & 31;
    int t    = w / 24;
    int slot = w - t * 24;
    int b = t / SEQ;
    int n = t - b * SEQ;

    float v0, v1;
    float* dst;
    bool dorope;
    float gain = 1.0f;

    if (slot < 16) {
        const float* src = g_qkv + (size_t)t * NQKV + slot * HD;
        v0 = src[lane]; v1 = src[lane + 32];
        dst = g_q + (((size_t)(b * NH + slot)) * SEQ + n) * HD;
        dorope = true; gain = 1.5f;
    } else if (slot < 20) {
        int h = slot - 16;
        const float* src = g_qkv + (size_t)t * NQKV + 1024 + h * HD;
        v0 = src[lane]; v1 = src[lane + 32];
        dst = g_k + (((size_t)(b * NHKV + h)) * SEQ + n) * HD;
        dorope = true;
    } else {
        int h = slot - 20;
        const float* src = g_qkv + (size_t)t * NQKV + 1280 + h * HD;
        v0 = src[lane]; v1 = src[lane + 32];
        dst = g_v + (((size_t)(b * NHKV + h)) * SEQ + n) * HD;
        dorope = false;
    }

    if (dorope) {
        float ss = v0*v0 + v1*v1;
#pragma unroll
        for (int o = 16; o; o >>= 1) ss += __shfl_xor_sync(0xffffffffu, ss, o);
        float r = rsqrtf(ss * (1.0f/64.0f) + 1.1920929e-7f);
        v0 *= r; v1 *= r;
        float inv_freq = powf(10000.0f, -(float)lane * (1.0f/32.0f));
        float ang = (float)n * inv_freq;
        float sv, cv;
        sincosf(ang, &sv, &cv);
        float o0 = v0*cv - v1*sv;
        float o1 = v1*cv + v0*sv;
        v0 = o0 * gain; v1 = o1 * gain;
    }
    dst[lane] = v0;
    dst[lane + 32] = v1;
}

// ---------------- tensor-core causal flash attention (tf32 mma.sync) -------
#define APAD 68
#define AKS(k,d) smA[(k)*APAD + (d)]
#define AVS(d,k) smA[64*APAD + (d)*APAD + (k)]
#define APS(r,c) smA[2*64*APAD + (r)*APAD + (c)]
#define ATTN_SMEM (3*64*APAD*4)

__global__ __launch_bounds__(128) void attn_mma_kernel()
{
    extern __shared__ uint32_t smA[];

    int qb = blockIdx.x, h = blockIdx.y, b = blockIdx.z;
    int tid = threadIdx.x;
    int wid = tid >> 5, lane = tid & 31;
    int gid = lane >> 2, tig = lane & 3;
    int r0 = wid * 16;
    int hkv = h >> 2;

    const float* qbase = g_q + ((size_t)(b*NH   + h  )) * SEQ * HD;
    const float* kbase = g_k + ((size_t)(b*NHKV + hkv)) * SEQ * HD;
    const float* vbase = g_v + ((size_t)(b*NHKV + hkv)) * SEQ * HD;

    int skey  = tid & 63;
    int shalf = tid >> 6;

    {
        const float* qr = qbase + (size_t)(qb*64 + skey) * HD + shalf*32;
#pragma unroll
        for (int i = 0; i < 8; i++) {
            float4 f = *(const float4*)(qr + i*4);
            int d = shalf*32 + i*4;
            APS(skey, d+0) = f2tf32(f.x * 0.125f);
            APS(skey, d+1) = f2tf32(f.y * 0.125f);
            APS(skey, d+2) = f2tf32(f.z * 0.125f);
            APS(skey, d+3) = f2tf32(f.w * 0.125f);
        }
    }
    __syncthreads();

    uint32_t qf[8][4];
#pragma unroll
    for (int ks = 0; ks < 8; ks++) {
        qf[ks][0] = APS(r0+gid,     ks*8+tig);
        qf[ks][1] = APS(r0+gid+8,   ks*8+tig);
        qf[ks][2] = APS(r0+gid,     ks*8+tig+4);
        qf[ks][3] = APS(r0+gid+8,   ks*8+tig+4);
    }

    float m0 = -1e30f, m1 = -1e30f, l0 = 0.f, l1 = 0.f;
    float o[8][4];
#pragma unroll
    for (int nt = 0; nt < 8; nt++)
#pragma unroll
        for (int j = 0; j < 4; j++) o[nt][j] = 0.f;

    int row0 = qb*64 + r0 + gid;
    int row1 = row0 + 8;

    for (int kt = 0; kt <= qb; kt++) {
        int k0 = kt * 64;
        __syncthreads();
        {
            const float* kr = kbase + (size_t)(k0 + skey) * HD + shalf*32;
            const float* vr = vbase + (size_t)(k0 + skey) * HD + shalf*32;
#pragma unroll
            for (int i = 0; i < 8; i++) {
                float4 f = *(const float4*)(kr + i*4);
                float4 g = *(const float4*)(vr + i*4);
                int d = shalf*32 + i*4;
                AKS(skey, d+0) = f2tf32(f.x);
                AKS(skey, d+1) = f2tf32(f.y);
                AKS(skey, d+2) = f2tf32(f.z);
                AKS(skey, d+3) = f2tf32(f.w);
                AVS(d+0, skey) = f2tf32(g.x);
                AVS(d+1, skey) = f2tf32(g.y);
                AVS(d+2, skey) = f2tf32(g.z);
                AVS(d+3, skey) = f2tf32(g.w);
            }
        }
        __syncthreads();

        float s[8][4];
#pragma unroll
        for (int nt = 0; nt < 8; nt++)
#pragma unroll
            for (int j = 0; j < 4; j++) s[nt][j] = 0.f;

#pragma unroll
        for (int ks = 0; ks < 8; ks++) {
#pragma unroll
            for (int nt = 0; nt < 8; nt++) {
                uint32_t b0 = AKS(nt*8+gid, ks*8+tig);
                uint32_t b1 = AKS(nt*8+gid, ks*8+tig+4);
                mma_tf32(s[nt][0], s[nt][1], s[nt][2], s[nt][3],
                         qf[ks][0], qf[ks][1], qf[ks][2], qf[ks][3], b0, b1);
            }
        }

        if (kt == qb) {
#pragma unroll
            for (int nt = 0; nt < 8; nt++) {
                int key = k0 + nt*8 + 2*tig;
                if (key     > row0) s[nt][0] = -1e30f;
                if (key + 1 > row0) s[nt][1] = -1e30f;
                if (key     > row1) s[nt][2] = -1e30f;
                if (key + 1 > row1) s[nt][3] = -1e30f;
            }
        }

        float mx0 = m0, mx1 = m1;
#pragma unroll
        for (int nt = 0; nt < 8; nt++) {
            mx0 = fmaxf(mx0, fmaxf(s[nt][0], s[nt][1]));
            mx1 = fmaxf(mx1, fmaxf(s[nt][2], s[nt][3]));
        }
        mx0 = fmaxf(mx0, __shfl_xor_sync(0xffffffffu, mx0, 1));
        mx0 = fmaxf(mx0, __shfl_xor_sync(0xffffffffu, mx0, 2));
        mx1 = fmaxf(mx1, __shfl_xor_sync(0xffffffffu, mx1, 1));
        mx1 = fmaxf(mx1, __shfl_xor_sync(0xffffffffu, mx1, 2));

        float c0 = __expf(m0 - mx0);
        float c1 = __expf(m1 - mx1);
        m0 = mx0; m1 = mx1;
        l0 *= c0;  l1 *= c1;
#pragma unroll
        for (int nt = 0; nt < 8; nt++) {
            o[nt][0] *= c0; o[nt][1] *= c0;
            o[nt][2] *= c1; o[nt][3] *= c1;
        }

        float ps0 = 0.f, ps1 = 0.f;
#pragma unroll
        for (int nt = 0; nt < 8; nt++) {
            s[nt][0] = __expf(s[nt][0] - mx0);
            s[nt][1] = __expf(s[nt][1] - mx0);
            s[nt][2] = __expf(s[nt][2] - mx1);
            s[nt][3] = __expf(s[nt][3] - mx1);
            ps0 += s[nt][0] + s[nt][1];
            ps1 += s[nt][2] + s[nt][3];
        }
        ps0 += __shfl_xor_sync(0xffffffffu, ps0, 1);
        ps0 += __shfl_xor_sync(0xffffffffu, ps0, 2);
        ps1 += __shfl_xor_sync(0xffffffffu, ps1, 1);
        ps1 += __shfl_xor_sync(0xffffffffu, ps1, 2);
        l0 += ps0; l1 += ps1;

#pragma unroll
        for (int nt = 0; nt < 8; nt++) {
            int c = nt*8 + 2*tig;
            APS(r0+gid,   c  ) = f2tf32(s[nt][0]);
            APS(r0+gid,   c+1) = f2tf32(s[nt][1]);
            APS(r0+gid+8, c  ) = f2tf32(s[nt][2]);
            APS(r0+gid+8, c+1) = f2tf32(s[nt][3]);
        }
        __syncwarp();

#pragma unroll
        for (int ks = 0; ks < 8; ks++) {
            uint32_t a0 = APS(r0+gid,   ks*8+tig);
            uint32_t a1 = APS(r0+gid+8, ks*8+tig);
            uint32_t a2 = APS(r0+gid,   ks*8+tig+4);
            uint32_t a3 = APS(r0+gid+8, ks*8+tig+4);
#pragma unroll
            for (int nt = 0; nt < 8; nt++) {
                uint32_t b0 = AVS(nt*8+gid, ks*8+tig);
                uint32_t b1 = AVS(nt*8+gid, ks*8+tig+4);
                mma_tf32(o[nt][0], o[nt][1], o[nt][2], o[nt][3],
                         a0, a1, a2, a3, b0, b1);
            }
        }
    }

    // finalize: divide by l, write tf32 bits into g_y[b][n][h][d]
    float i0 = 1.0f / l0, i1 = 1.0f / l1;
    uint32_t* y0 = g_y + (((size_t)(b*SEQ + row0)) * NH + h) * HD;
    uint32_t* y1 = g_y + (((size_t)(b*SEQ + row1)) * NH + h) * HD;
#pragma unroll
    for (int nt = 0; nt < 8; nt++) {
        int c = nt*8 + 2*tig;
        y0[c]   = f2tf32(o[nt][0] * i0);
        y0[c+1] = f2tf32(o[nt][1] * i0);
        y1[c]   = f2tf32(o[nt][2] * i1);
        y1[c+1] = f2tf32(o[nt][3] * i1);
    }
}

// ---------------- launch ----------------------------------------------------
extern "C" void kernel_launch(void* const* d_in, const int* in_sizes, int n_in,
                              void* d_out, int out_size)
{
    const float* x  = (const float*)d_in[0];
    const float* wq = (const float*)d_in[1];
    const float* wk = (const float*)d_in[2];
    const float* wv = (const float*)d_in[3];
    const float* wo = (const float*)d_in[4];
    float* out = (float*)d_out;

    uint32_t *xc, *wqkvT, *woT, *yy;
    float *qkv;
    cudaGetSymbolAddress((void**)&xc,    g_xc);
    cudaGetSymbolAddress((void**)&qkv,   g_qkv);
    cudaGetSymbolAddress((void**)&wqkvT, g_wqkvT);
    cudaGetSymbolAddress((void**)&woT,   g_woT);
    cudaGetSymbolAddress((void**)&yy,    g_y);

    cudaFuncSetAttribute(mma_gemm_kernel, cudaFuncAttributeMaxDynamicSharedMemorySize, GEMM_SMEM);
    cudaFuncSetAttribute(attn_mma_kernel, cudaFuncAttributeMaxDynamicSharedMemorySize, ATTN_SMEM);

    // x -> tf32 bits
    xconv_kernel<<<TOK*CDIM/(256*4), 256>>>(x);

    // weight transposes -> [N,K] tf32 bits (qkv fused)
    transpose_kernel<<<dim3(32,32), dim3(32,8)>>>(wq, wqkvT,              CDIM, CDIM);
    transpose_kernel<<<dim3(8, 32), dim3(32,8)>>>(wk, wqkvT + 1024*CDIM,  CDIM, NHKV*HD);
    transpose_kernel<<<dim3(8, 32), dim3(32,8)>>>(wv, wqkvT + 1280*CDIM,  CDIM, NHKV*HD);
    transpose_kernel<<<dim3(32,32), dim3(32,8)>>>(wo, woT,                CDIM, CDIM);

    // fused QKV projection
    mma_gemm_kernel<<<dim3(NQKV/128, TOK/128), 256, GEMM_SMEM>>>(xc, wqkvT, qkv, NQKV);

    // RMSNorm + RoPE + transpose
    pack_kernel<<<(TOK*24)/8, 256>>>();

    // causal SDPA (tensor cores)
    attn_mma_kernel<<<dim3(SEQ/64, NH, BATCH), 128, ATTN_SMEM>>>();

    // output projection
    mma_gemm_kernel<<<dim3(CDIM/128, TOK/128), 256, GEMM_SMEM>>>(yy, woT, out, CDIM);
}

// round 6
// speedup vs baseline: 6.4085x; 1.9078x over previous
#include <cuda_runtime.h>
#include <cuda_fp16.h>
#include <math.h>
#include <stdint.h>

// ---------------- problem constants ----------------
#define BATCH 4
#define SEQ   2048
#define CDIM  1024
#define NH    16
#define NHKV  4
#define HD    64
#define TOK   (BATCH*SEQ)          // 8192
#define GKW   512                  // K dim in half2 words (1024 halves)
#define NQKV  1536                 // 1024 + 256 + 256

// ---------------- scratch (device globals) ----------------
__device__ uint32_t g_xh  [TOK*GKW];         // x as half2 words
__device__ float    g_qkv [TOK*NQKV];        // fused qkv projection (fp32)
__device__ __half   g_qh [BATCH*NH*SEQ*HD];  // q half, scale folded (1.5/8)
__device__ __half   g_kh [BATCH*NHKV*SEQ*HD];// k half [b,hkv][n][d]
__device__ __half   g_vt [BATCH*NHKV*HD*SEQ];// v half transposed [b,hkv][d][n]
__device__ uint32_t g_y  [TOK*GKW];          // attention out, half2 words
__device__ uint32_t g_wqkvT[NQKV*GKW];       // [N,K] transposed weights half2
__device__ uint32_t g_woT  [CDIM*GKW];

// ---------------- helpers ----------------
__device__ __forceinline__ uint32_t smem_u32(const void* p) {
    uint32_t a;
    asm("{ .reg .u64 t; cvta.to.shared.u64 t, %1; cvt.u32.u64 %0, t; }" : "=r"(a) : "l"(p));
    return a;
}
__device__ __forceinline__ uint32_t f2h2(float lo, float hi) {
    __half2 h = __floats2half2_rn(lo, hi);
    return *(uint32_t*)&h;
}
__device__ __forceinline__ void mma_f16(float& d0, float& d1, float& d2, float& d3,
                                        uint32_t a0, uint32_t a1, uint32_t a2, uint32_t a3,
                                        uint32_t b0, uint32_t b1) {
    asm volatile(
        "mma.sync.aligned.m16n8k16.row.col.f32.f16.f16.f32 "
        "{%0,%1,%2,%3}, {%4,%5,%6,%7}, {%8,%9}, {%0,%1,%2,%3};"
        : "+f"(d0), "+f"(d1), "+f"(d2), "+f"(d3)
        : "r"(a0), "r"(a1), "r"(a2), "r"(a3), "r"(b0), "r"(b1));
}
#define CP_ASYNC16(saddr, gptr) \
    asm volatile("cp.async.cg.shared.global [%0], [%1], 16;" :: "r"(saddr), "l"(gptr))
#define CP_COMMIT()  asm volatile("cp.async.commit_group;" ::: "memory")
#define CP_WAIT(n)   asm volatile("cp.async.wait_group %0;" :: "n"(n) : "memory")

// ---------------- x -> half2 words -----------------------------------------
__global__ __launch_bounds__(256) void xconv_kernel(const float* __restrict__ x)
{
    int i = (blockIdx.x * 256 + threadIdx.x) * 4;     // float index
    float4 f = *(const float4*)(x + i);
    uint2 u;
    u.x = f2h2(f.x, f.y);
    u.y = f2h2(f.z, f.w);
    *(uint2*)(g_xh + i/2) = u;
}

// ---------------- weight transpose (+half): D[c][r] = h(S[r][c]) -----------
__global__ __launch_bounds__(256) void transpose_kernel(
    const float* __restrict__ S, __half* __restrict__ D, int R, int Ccols)
{
    __shared__ float t[32][33];
    int bx = blockIdx.x * 32, by = blockIdx.y * 32;
#pragma unroll
    for (int i = 0; i < 32; i += 8)
        t[threadIdx.y + i][threadIdx.x] = S[(size_t)(by + threadIdx.y + i) * Ccols + bx + threadIdx.x];
    __syncthreads();
#pragma unroll
    for (int i = 0; i < 32; i += 8)
        D[(size_t)(bx + threadIdx.y + i) * R + by + threadIdx.x] = __float2half(t[threadIdx.x][threadIdx.y + i]);
}

// ---------------- fp16 GEMM, cp.async 3-stage pipeline ----------------------
// C[M,Np] = A[M,1024] @ Bt[Np,1024]^T.  A,Bt half2 words. CTA 128x128x64h.
#define GS   3
#define GBK  32                       // words (64 halves) per chunk
#define GSTR 36                       // padded smem row stride (words)
#define STAGE_W (128*GSTR)
#define GEMM_SMEM (2*GS*STAGE_W*4)    // 110592 B

__global__ __launch_bounds__(256) void mma_gemm_kernel(
    const uint32_t* __restrict__ A, const uint32_t* __restrict__ Bt,
    float* __restrict__ C, int Np)
{
    extern __shared__ uint32_t gsm[];
    uint32_t* As = gsm;
    uint32_t* Bs = gsm + GS*STAGE_W;

    int tid  = threadIdx.x;
    int wid  = tid >> 5, lane = tid & 31;
    int gid  = lane >> 2, tig = lane & 3;
    int wm   = (wid & 1) * 64;
    int wn   = (wid >> 1) * 32;

    int lr = tid >> 1;            // row 0..127
    int lc = (tid & 1) * 16;      // word col base 0/16

    const uint32_t* Ag = A  + (size_t)blockIdx.y * 128 * GKW + (size_t)lr * GKW + lc;
    const uint32_t* Bg = Bt + (size_t)blockIdx.x * 128 * GKW + (size_t)lr * GKW + lc;

    uint32_t sA = smem_u32(As) + (uint32_t)(lr * GSTR + lc) * 4u;
    uint32_t sB = smem_u32(Bs) + (uint32_t)(lr * GSTR + lc) * 4u;
    const uint32_t stageB = STAGE_W * 4u;

    float acc[4][4][4];
#pragma unroll
    for (int i = 0; i < 4; i++)
#pragma unroll
        for (int j = 0; j < 4; j++)
#pragma unroll
            for (int r = 0; r < 4; r++) acc[i][j][r] = 0.f;

    const int NIT = GKW / GBK;    // 16

#pragma unroll
    for (int s = 0; s < GS-1; s++) {
#pragma unroll
        for (int i = 0; i < 4; i++) {
            CP_ASYNC16(sA + s*stageB + i*16, Ag + s*GBK + i*4);
            CP_ASYNC16(sB + s*stageB + i*16, Bg + s*GBK + i*4);
        }
        CP_COMMIT();
    }

    for (int c = 0; c < NIT; c++) {
        CP_WAIT(GS-2);
        __syncthreads();

        int nc = c + GS - 1;
        if (nc < NIT) {
            int s = nc % GS;
#pragma unroll
            for (int i = 0; i < 4; i++) {
                CP_ASYNC16(sA + s*stageB + i*16, Ag + nc*GBK + i*4);
                CP_ASYNC16(sB + s*stageB + i*16, Bg + nc*GBK + i*4);
            }
            CP_COMMIT();
        }

        const uint32_t* Ab_ = As + (c % GS) * STAGE_W;
        const uint32_t* Bb_ = Bs + (c % GS) * STAGE_W;

#pragma unroll
        for (int kk = 0; kk < 4; kk++) {          // 4 k16-steps per chunk
            int kb = kk * 8;
            uint32_t af[4][4], bf[4][2];
#pragma unroll
            for (int mt = 0; mt < 4; mt++) {
                int r0 = (wm + mt*16 + gid) * GSTR;
                af[mt][0] = Ab_[r0          + kb + tig];
                af[mt][1] = Ab_[r0 + 8*GSTR + kb + tig];
                af[mt][2] = Ab_[r0          + kb + tig + 4];
                af[mt][3] = Ab_[r0 + 8*GSTR + kb + tig + 4];
            }
#pragma unroll
            for (int nt = 0; nt < 4; nt++) {
                int n0 = (wn + nt*8 + gid) * GSTR;
                bf[nt][0] = Bb_[n0 + kb + tig];
                bf[nt][1] = Bb_[n0 + kb + tig + 4];
            }
#pragma unroll
            for (int mt = 0; mt < 4; mt++)
#pragma unroll
                for (int nt = 0; nt < 4; nt++)
                    mma_f16(acc[mt][nt][0], acc[mt][nt][1], acc[mt][nt][2], acc[mt][nt][3],
                            af[mt][0], af[mt][1], af[mt][2], af[mt][3],
                            bf[nt][0], bf[nt][1]);
        }
    }

    int baseRow = blockIdx.y * 128 + wm;
    int baseCol = blockIdx.x * 128 + wn;
#pragma unroll
    for (int mt = 0; mt < 4; mt++) {
#pragma unroll
        for (int nt = 0; nt < 4; nt++) {
            int row = baseRow + mt * 16 + gid;
            int col = baseCol + nt * 8 + tig * 2;
            *(float2*)(C + (size_t)row * Np + col)       = make_float2(acc[mt][nt][0], acc[mt][nt][1]);
            *(float2*)(C + (size_t)(row + 8) * Np + col) = make_float2(acc[mt][nt][2], acc[mt][nt][3]);
        }
    }
}

// ---------------- pack: RMSNorm + RoPE (+gain) -> half layouts --------------
__global__ __launch_bounds__(256) void pack_kernel()
{
    int w    = (blockIdx.x * 256 + threadIdx.x) >> 5;
    int lane = threadIdx.x & 31;
    int t    = w / 24;
    int slot = w - t * 24;
    int b = t / SEQ;
    int n = t - b * SEQ;

    float v0, v1;
    bool dorope;
    float gain = 1.0f;
    __half* dst = 0;
    __half* dstT = 0;

    if (slot < 16) {
        const float* src = g_qkv + (size_t)t * NQKV + slot * HD;
        v0 = src[lane]; v1 = src[lane + 32];
        dst = g_qh + (((size_t)(b * NH + slot)) * SEQ + n) * HD;
        dorope = true; gain = 1.5f * 0.125f;        // qk-gain * 1/sqrt(D) folded
    } else if (slot < 20) {
        int h = slot - 16;
        const float* src = g_qkv + (size_t)t * NQKV + 1024 + h * HD;
        v0 = src[lane]; v1 = src[lane + 32];
        dst = g_kh + (((size_t)(b * NHKV + h)) * SEQ + n) * HD;
        dorope = true;
    } else {
        int h = slot - 20;
        const float* src = g_qkv + (size_t)t * NQKV + 1280 + h * HD;
        v0 = src[lane]; v1 = src[lane + 32];
        dstT = g_vt + ((size_t)(b * NHKV + h)) * HD * SEQ;
        dorope = false;
    }

    if (dorope) {
        float ss = v0*v0 + v1*v1;
#pragma unroll
        for (int o = 16; o; o >>= 1) ss += __shfl_xor_sync(0xffffffffu, ss, o);
        float r = rsqrtf(ss * (1.0f/64.0f) + 1.1920929e-7f);
        v0 *= r; v1 *= r;
        float inv_freq = powf(10000.0f, -(float)lane * (1.0f/32.0f));
        float ang = (float)n * inv_freq;
        float sv, cv;
        sincosf(ang, &sv, &cv);
        float o0 = v0*cv - v1*sv;
        float o1 = v1*cv + v0*sv;
        v0 = o0 * gain; v1 = o1 * gain;
        dst[lane]      = __float2half(v0);
        dst[lane + 32] = __float2half(v1);
    } else {
        dstT[(size_t)lane      * SEQ + n] = __float2half(v0);
        dstT[(size_t)(lane+32) * SEQ + n] = __float2half(v1);
    }
}

// ---------------- fp16 tensor-core causal flash attention -------------------
// CTA: 64 q-rows, 4 warps x 16 rows, K-tiles of 64 keys. Word stride 36.
#define ASTR 36
#define AKS(k,wd) smA[(k)*ASTR + (wd)]
#define AVS(d,wd) smA[64*ASTR + (d)*ASTR + (wd)]
#define APS(r,wd) smA[2*64*ASTR + (r)*ASTR + (wd)]
#define ATTN_SMEM (3*64*ASTR*4)

__global__ __launch_bounds__(128) void attn_mma_kernel()
{
    extern __shared__ uint32_t smA[];

    int qb = blockIdx.x, h = blockIdx.y, b = blockIdx.z;
    int tid = threadIdx.x;
    int wid = tid >> 5, lane = tid & 31;
    int gid = lane >> 2, tig = lane & 3;
    int r0 = wid * 16;
    int hkv = h >> 2;

    const __half* qbase = g_qh + ((size_t)(b*NH   + h  )) * SEQ * HD;
    const __half* kbase = g_kh + ((size_t)(b*NHKV + hkv)) * SEQ * HD;
    const __half* vtb   = g_vt + ((size_t)(b*NHKV + hkv)) * HD * SEQ;

    int srow  = tid & 63;
    int shalf = tid >> 6;

    // ---- stage Q (already scaled) into Ps region
    {
        const uint4* qr = (const uint4*)(qbase + (size_t)(qb*64 + srow) * HD + shalf*32);
#pragma unroll
        for (int i = 0; i < 4; i++)
            *(uint4*)&APS(srow, shalf*16 + i*4) = qr[i];
    }
    __syncthreads();

    uint32_t qf[4][4];
#pragma unroll
    for (int ks = 0; ks < 4; ks++) {
        qf[ks][0] = APS(r0+gid,   ks*8+tig);
        qf[ks][1] = APS(r0+gid+8, ks*8+tig);
        qf[ks][2] = APS(r0+gid,   ks*8+tig+4);
        qf[ks][3] = APS(r0+gid+8, ks*8+tig+4);
    }

    float m0 = -1e30f, m1 = -1e30f, l0 = 0.f, l1 = 0.f;
    float o[8][4];
#pragma unroll
    for (int nt = 0; nt < 8; nt++)
#pragma unroll
        for (int j = 0; j < 4; j++) o[nt][j] = 0.f;

    int row0 = qb*64 + r0 + gid;
    int row1 = row0 + 8;

    for (int kt = 0; kt <= qb; kt++) {
        int k0 = kt * 64;
        __syncthreads();
        {   // stage K [key][dim] and V^T [dim][key]
            const uint4* kr = (const uint4*)(kbase + (size_t)(k0 + srow) * HD + shalf*32);
            const uint4* vr = (const uint4*)(vtb + (size_t)srow * SEQ + k0 + shalf*32);
#pragma unroll
            for (int i = 0; i < 4; i++) {
                *(uint4*)&AKS(srow, shalf*16 + i*4) = kr[i];
                *(uint4*)&AVS(srow, shalf*16 + i*4) = vr[i];
            }
        }
        __syncthreads();

        // ---- scores S = Q @ K^T
        float s[8][4];
#pragma unroll
        for (int nt = 0; nt < 8; nt++)
#pragma unroll
            for (int j = 0; j < 4; j++) s[nt][j] = 0.f;

#pragma unroll
        for (int ks = 0; ks < 4; ks++) {
#pragma unroll
            for (int nt = 0; nt < 8; nt++) {
                uint32_t b0 = AKS(nt*8+gid, ks*8+tig);
                uint32_t b1 = AKS(nt*8+gid, ks*8+tig+4);
                mma_f16(s[nt][0], s[nt][1], s[nt][2], s[nt][3],
                        qf[ks][0], qf[ks][1], qf[ks][2], qf[ks][3], b0, b1);
            }
        }

        if (kt == qb) {
#pragma unroll
            for (int nt = 0; nt < 8; nt++) {
                int key = k0 + nt*8 + 2*tig;
                if (key     > row0) s[nt][0] = -1e30f;
                if (key + 1 > row0) s[nt][1] = -1e30f;
                if (key     > row1) s[nt][2] = -1e30f;
                if (key + 1 > row1) s[nt][3] = -1e30f;
            }
        }

        float mx0 = m0, mx1 = m1;
#pragma unroll
        for (int nt = 0; nt < 8; nt++) {
            mx0 = fmaxf(mx0, fmaxf(s[nt][0], s[nt][1]));
            mx1 = fmaxf(mx1, fmaxf(s[nt][2], s[nt][3]));
        }
        mx0 = fmaxf(mx0, __shfl_xor_sync(0xffffffffu, mx0, 1));
        mx0 = fmaxf(mx0, __shfl_xor_sync(0xffffffffu, mx0, 2));
        mx1 = fmaxf(mx1, __shfl_xor_sync(0xffffffffu, mx1, 1));
        mx1 = fmaxf(mx1, __shfl_xor_sync(0xffffffffu, mx1, 2));

        float c0 = __expf(m0 - mx0);
        float c1 = __expf(m1 - mx1);
        m0 = mx0; m1 = mx1;
        l0 *= c0;  l1 *= c1;
#pragma unroll
        for (int nt = 0; nt < 8; nt++) {
            o[nt][0] *= c0; o[nt][1] *= c0;
            o[nt][2] *= c1; o[nt][3] *= c1;
        }

        float ps0 = 0.f, ps1 = 0.f;
#pragma unroll
        for (int nt = 0; nt < 8; nt++) {
            s[nt][0] = __expf(s[nt][0] - mx0);
            s[nt][1] = __expf(s[nt][1] - mx0);
            s[nt][2] = __expf(s[nt][2] - mx1);
            s[nt][3] = __expf(s[nt][3] - mx1);
            ps0 += s[nt][0] + s[nt][1];
            ps1 += s[nt][2] + s[nt][3];
        }
        ps0 += __shfl_xor_sync(0xffffffffu, ps0, 1);
        ps0 += __shfl_xor_sync(0xffffffffu, ps0, 2);
        ps1 += __shfl_xor_sync(0xffffffffu, ps1, 1);
        ps1 += __shfl_xor_sync(0xffffffffu, ps1, 2);
        l0 += ps0; l1 += ps1;

        // ---- P -> smem as half2 (warp-private rows)
#pragma unroll
        for (int nt = 0; nt < 8; nt++) {
            APS(r0+gid,   nt*4+tig) = f2h2(s[nt][0], s[nt][1]);
            APS(r0+gid+8, nt*4+tig) = f2h2(s[nt][2], s[nt][3]);
        }
        __syncwarp();

        // ---- O += P @ V
#pragma unroll
        for (int ks = 0; ks < 4; ks++) {
            uint32_t a0 = APS(r0+gid,   ks*8+tig);
            uint32_t a1 = APS(r0+gid+8, ks*8+tig);
            uint32_t a2 = APS(r0+gid,   ks*8+tig+4);
            uint32_t a3 = APS(r0+gid+8, ks*8+tig+4);
#pragma unroll
            for (int nt = 0; nt < 8; nt++) {
                uint32_t b0 = AVS(nt*8+gid, ks*8+tig);
                uint32_t b1 = AVS(nt*8+gid, ks*8+tig+4);
                mma_f16(o[nt][0], o[nt][1], o[nt][2], o[nt][3],
                        a0, a1, a2, a3, b0, b1);
            }
        }
    }

    // ---- finalize: divide by l, write half2 words into g_y[b][n][h][d]
    float i0 = 1.0f / l0, i1 = 1.0f / l1;
    uint32_t* y0 = g_y + (((size_t)(b*SEQ + row0)) * NH + h) * (HD/2);
    uint32_t* y1 = g_y + (((size_t)(b*SEQ + row1)) * NH + h) * (HD/2);
#pragma unroll
    for (int nt = 0; nt < 8; nt++) {
        y0[nt*4+tig] = f2h2(o[nt][0] * i0, o[nt][1] * i0);
        y1[nt*4+tig] = f2h2(o[nt][2] * i1, o[nt][3] * i1);
    }
}

// ---------------- launch ----------------------------------------------------
extern "C" void kernel_launch(void* const* d_in, const int* in_sizes, int n_in,
                              void* d_out, int out_size)
{
    const float* x  = (const float*)d_in[0];
    const float* wq = (const float*)d_in[1];
    const float* wk = (const float*)d_in[2];
    const float* wv = (const float*)d_in[3];
    const float* wo = (const float*)d_in[4];
    float* out = (float*)d_out;

    uint32_t *xh, *wqkvT, *woT, *yy;
    float *qkv;
    cudaGetSymbolAddress((void**)&xh,    g_xh);
    cudaGetSymbolAddress((void**)&qkv,   g_qkv);
    cudaGetSymbolAddress((void**)&wqkvT, g_wqkvT);
    cudaGetSymbolAddress((void**)&woT,   g_woT);
    cudaGetSymbolAddress((void**)&yy,    g_y);

    cudaFuncSetAttribute(mma_gemm_kernel, cudaFuncAttributeMaxDynamicSharedMemorySize, GEMM_SMEM);
    cudaFuncSetAttribute(attn_mma_kernel, cudaFuncAttributeMaxDynamicSharedMemorySize, ATTN_SMEM);

    // x -> half
    xconv_kernel<<<TOK*CDIM/(256*4), 256>>>(x);

    // weight transposes -> [N,K] half (qkv fused)
    transpose_kernel<<<dim3(32,32), dim3(32,8)>>>(wq, (__half*)wqkvT,               CDIM, CDIM);
    transpose_kernel<<<dim3(8, 32), dim3(32,8)>>>(wk, (__half*)(wqkvT + 1024*GKW),  CDIM, NHKV*HD);
    transpose_kernel<<<dim3(8, 32), dim3(32,8)>>>(wv, (__half*)(wqkvT + 1280*GKW),  CDIM, NHKV*HD);
    transpose_kernel<<<dim3(32,32), dim3(32,8)>>>(wo, (__half*)woT,                 CDIM, CDIM);

    // fused QKV projection
    mma_gemm_kernel<<<dim3(NQKV/128, TOK/128), 256, GEMM_SMEM>>>(xh, wqkvT, qkv, NQKV);

    // RMSNorm + RoPE + layouts
    pack_kernel<<<(TOK*24)/8, 256>>>();

    // causal SDPA (fp16 tensor cores)
    attn_mma_kernel<<<dim3(SEQ/64, NH, BATCH), 128, ATTN_SMEM>>>();

    // output projection
    mma_gemm_kernel<<<dim3(CDIM/128, TOK/128), 256, GEMM_SMEM>>>(yy, woT, out, CDIM);
}

// round 7
// speedup vs baseline: 7.9623x; 1.2425x over previous
#include <cuda_runtime.h>
#include <cuda_fp16.h>
#include <math.h>
#include <stdint.h>

// ---------------- problem constants ----------------
#define BATCH 4
#define SEQ   2048
#define CDIM  1024
#define NH    16
#define NHKV  4
#define HD    64
#define TOK   (BATCH*SEQ)          // 8192
#define GKW   512                  // K dim in half2 words (1024 halves)
#define NQKV  1536                 // 1024 + 256 + 256

// ---------------- scratch (device globals) ----------------
__device__ uint32_t g_xh  [TOK*GKW];         // x as half2 words
__device__ float    g_qkv [TOK*NQKV];        // fused qkv projection (fp32)
__device__ __half   g_qh [BATCH*NH*SEQ*HD];  // q half, scale folded (1.5/8)
__device__ __half   g_kh [BATCH*NHKV*SEQ*HD];// k half [b,hkv][n][d]
__device__ __half   g_vt [BATCH*NHKV*HD*SEQ];// v half transposed [b,hkv][d][n]
__device__ uint32_t g_y  [TOK*GKW];          // attention out, half2 words
__device__ uint32_t g_wqkvT[NQKV*GKW];       // [N,K] transposed weights half2
__device__ uint32_t g_woT  [CDIM*GKW];

// ---------------- helpers ----------------
__device__ __forceinline__ uint32_t smem_u32(const void* p) {
    uint32_t a;
    asm("{ .reg .u64 t; cvta.to.shared.u64 t, %1; cvt.u32.u64 %0, t; }" : "=r"(a) : "l"(p));
    return a;
}
__device__ __forceinline__ uint32_t f2h2(float lo, float hi) {
    __half2 h = __floats2half2_rn(lo, hi);
    return *(uint32_t*)&h;
}
__device__ __forceinline__ void mma_f16(float& d0, float& d1, float& d2, float& d3,
                                        uint32_t a0, uint32_t a1, uint32_t a2, uint32_t a3,
                                        uint32_t b0, uint32_t b1) {
    asm volatile(
        "mma.sync.aligned.m16n8k16.row.col.f32.f16.f16.f32 "
        "{%0,%1,%2,%3}, {%4,%5,%6,%7}, {%8,%9}, {%0,%1,%2,%3};"
        : "+f"(d0), "+f"(d1), "+f"(d2), "+f"(d3)
        : "r"(a0), "r"(a1), "r"(a2), "r"(a3), "r"(b0), "r"(b1));
}
#define CP_ASYNC16(saddr, gptr) \
    asm volatile("cp.async.cg.shared.global [%0], [%1], 16;" :: "r"(saddr), "l"(gptr))
#define CP_COMMIT()  asm volatile("cp.async.commit_group;" ::: "memory")
#define CP_WAIT(n)   asm volatile("cp.async.wait_group %0;" :: "n"(n) : "memory")

// ---------------- x -> half2 words -----------------------------------------
__global__ __launch_bounds__(256) void xconv_kernel(const float* __restrict__ x)
{
    int i = (blockIdx.x * 256 + threadIdx.x) * 4;
    float4 f = *(const float4*)(x + i);
    uint2 u;
    u.x = f2h2(f.x, f.y);
    u.y = f2h2(f.z, f.w);
    *(uint2*)(g_xh + i/2) = u;
}

// ---------------- weight transpose (+half): D[c][r] = h(S[r][c]) -----------
__global__ __launch_bounds__(256) void transpose_kernel(
    const float* __restrict__ S, __half* __restrict__ D, int R, int Ccols)
{
    __shared__ float t[32][33];
    int bx = blockIdx.x * 32, by = blockIdx.y * 32;
#pragma unroll
    for (int i = 0; i < 32; i += 8)
        t[threadIdx.y + i][threadIdx.x] = S[(size_t)(by + threadIdx.y + i) * Ccols + bx + threadIdx.x];
    __syncthreads();
#pragma unroll
    for (int i = 0; i < 32; i += 8)
        D[(size_t)(bx + threadIdx.y + i) * R + by + threadIdx.x] = __float2half(t[threadIdx.x][threadIdx.y + i]);
}

// ---------------- fp16 GEMM, cp.async 3-stage pipeline ----------------------
#define GS   3
#define GBK  32
#define GSTR 36
#define STAGE_W (128*GSTR)
#define GEMM_SMEM (2*GS*STAGE_W*4)

__global__ __launch_bounds__(256) void mma_gemm_kernel(
    const uint32_t* __restrict__ A, const uint32_t* __restrict__ Bt,
    float* __restrict__ C, int Np)
{
    extern __shared__ uint32_t gsm[];
    uint32_t* As = gsm;
    uint32_t* Bs = gsm + GS*STAGE_W;

    int tid  = threadIdx.x;
    int wid  = tid >> 5, lane = tid & 31;
    int gid  = lane >> 2, tig = lane & 3;
    int wm   = (wid & 1) * 64;
    int wn   = (wid >> 1) * 32;

    int lr = tid >> 1;
    int lc = (tid & 1) * 16;

    const uint32_t* Ag = A  + (size_t)blockIdx.y * 128 * GKW + (size_t)lr * GKW + lc;
    const uint32_t* Bg = Bt + (size_t)blockIdx.x * 128 * GKW + (size_t)lr * GKW + lc;

    uint32_t sA = smem_u32(As) + (uint32_t)(lr * GSTR + lc) * 4u;
    uint32_t sB = smem_u32(Bs) + (uint32_t)(lr * GSTR + lc) * 4u;
    const uint32_t stageB = STAGE_W * 4u;

    float acc[4][4][4];
#pragma unroll
    for (int i = 0; i < 4; i++)
#pragma unroll
        for (int j = 0; j < 4; j++)
#pragma unroll
            for (int r = 0; r < 4; r++) acc[i][j][r] = 0.f;

    const int NIT = GKW / GBK;

#pragma unroll
    for (int s = 0; s < GS-1; s++) {
#pragma unroll
        for (int i = 0; i < 4; i++) {
            CP_ASYNC16(sA + s*stageB + i*16, Ag + s*GBK + i*4);
            CP_ASYNC16(sB + s*stageB + i*16, Bg + s*GBK + i*4);
        }
        CP_COMMIT();
    }

    for (int c = 0; c < NIT; c++) {
        CP_WAIT(GS-2);
        __syncthreads();

        int nc = c + GS - 1;
        if (nc < NIT) {
            int s = nc % GS;
#pragma unroll
            for (int i = 0; i < 4; i++) {
                CP_ASYNC16(sA + s*stageB + i*16, Ag + nc*GBK + i*4);
                CP_ASYNC16(sB + s*stageB + i*16, Bg + nc*GBK + i*4);
            }
            CP_COMMIT();
        }

        const uint32_t* Ab_ = As + (c % GS) * STAGE_W;
        const uint32_t* Bb_ = Bs + (c % GS) * STAGE_W;

#pragma unroll
        for (int kk = 0; kk < 4; kk++) {
            int kb = kk * 8;
            uint32_t af[4][4], bf[4][2];
#pragma unroll
            for (int mt = 0; mt < 4; mt++) {
                int r0 = (wm + mt*16 + gid) * GSTR;
                af[mt][0] = Ab_[r0          + kb + tig];
                af[mt][1] = Ab_[r0 + 8*GSTR + kb + tig];
                af[mt][2] = Ab_[r0          + kb + tig + 4];
                af[mt][3] = Ab_[r0 + 8*GSTR + kb + tig + 4];
            }
#pragma unroll
            for (int nt = 0; nt < 4; nt++) {
                int n0 = (wn + nt*8 + gid) * GSTR;
                bf[nt][0] = Bb_[n0 + kb + tig];
                bf[nt][1] = Bb_[n0 + kb + tig + 4];
            }
#pragma unroll
            for (int mt = 0; mt < 4; mt++)
#pragma unroll
                for (int nt = 0; nt < 4; nt++)
                    mma_f16(acc[mt][nt][0], acc[mt][nt][1], acc[mt][nt][2], acc[mt][nt][3],
                            af[mt][0], af[mt][1], af[mt][2], af[mt][3],
                            bf[nt][0], bf[nt][1]);
        }
    }

    int baseRow = blockIdx.y * 128 + wm;
    int baseCol = blockIdx.x * 128 + wn;
#pragma unroll
    for (int mt = 0; mt < 4; mt++) {
#pragma unroll
        for (int nt = 0; nt < 4; nt++) {
            int row = baseRow + mt * 16 + gid;
            int col = baseCol + nt * 8 + tig * 2;
            *(float2*)(C + (size_t)row * Np + col)       = make_float2(acc[mt][nt][0], acc[mt][nt][1]);
            *(float2*)(C + (size_t)(row + 8) * Np + col) = make_float2(acc[mt][nt][2], acc[mt][nt][3]);
        }
    }
}

// ---------------- pack: RMSNorm + RoPE (+gain) for q/k only ----------------
__global__ __launch_bounds__(256) void pack_kernel()
{
    int w    = (blockIdx.x * 256 + threadIdx.x) >> 5;
    int lane = threadIdx.x & 31;
    int t    = w / 20;
    int slot = w - t * 20;
    int b = t / SEQ;
    int n = t - b * SEQ;

    float v0, v1;
    float gain;
    __half* dst;

    if (slot < 16) {
        const float* src = g_qkv + (size_t)t * NQKV + slot * HD;
        v0 = src[lane]; v1 = src[lane + 32];
        dst = g_qh + (((size_t)(b * NH + slot)) * SEQ + n) * HD;
        gain = 1.5f * 0.125f;
    } else {
        int h = slot - 16;
        const float* src = g_qkv + (size_t)t * NQKV + 1024 + h * HD;
        v0 = src[lane]; v1 = src[lane + 32];
        dst = g_kh + (((size_t)(b * NHKV + h)) * SEQ + n) * HD;
        gain = 1.0f;
    }

    float ss = v0*v0 + v1*v1;
#pragma unroll
    for (int o = 16; o; o >>= 1) ss += __shfl_xor_sync(0xffffffffu, ss, o);
    float r = rsqrtf(ss * (1.0f/64.0f) + 1.1920929e-7f);
    v0 *= r; v1 *= r;
    float inv_freq = powf(10000.0f, -(float)lane * (1.0f/32.0f));
    float ang = (float)n * inv_freq;
    float sv, cv;
    sincosf(ang, &sv, &cv);
    float o0 = v0*cv - v1*sv;
    float o1 = v1*cv + v0*sv;
    dst[lane]      = __float2half(o0 * gain);
    dst[lane + 32] = __float2half(o1 * gain);
}

// ---------------- V transpose: g_qkv v-section -> g_vt [b,h][d][n] ----------
__global__ __launch_bounds__(256) void vtrans_kernel()
{
    __shared__ float t[32][33];
    int z  = blockIdx.z;             // b*NHKV + h
    int d0 = blockIdx.y * 32;
    int n0 = blockIdx.x * 32;
    int b  = z >> 2, h = z & 3;
    int tx = threadIdx.x, ty = threadIdx.y;

    const float* src = g_qkv + 1280 + h * HD + d0 + tx;
#pragma unroll
    for (int i = 0; i < 32; i += 8)
        t[ty + i][tx] = src[(size_t)(b*SEQ + n0 + ty + i) * NQKV];
    __syncthreads();

    __half* dst = g_vt + (size_t)z * HD * SEQ + n0 + tx;
#pragma unroll
    for (int i = 0; i < 32; i += 8)
        dst[(size_t)(d0 + ty + i) * SEQ] = __float2half(t[tx][ty + i]);
}

// ---------------- fp16 tensor-core causal flash attention -------------------
// CTA: 128 q-rows, 8 warps x 16 rows, K-tiles of 64 keys. Word stride 36.
#define ASTR 36
#define AKS(k,wd) smA[(k)*ASTR + (wd)]
#define AVS(d,wd) smA[64*ASTR + (d)*ASTR + (wd)]
#define APS(r,wd) smA[128*ASTR + (r)*ASTR + (wd)]
#define ATTN_SMEM (256*ASTR*4)

__global__ __launch_bounds__(256) void attn_mma_kernel()
{
    extern __shared__ uint32_t smA[];

    int qb = blockIdx.x, h = blockIdx.y, b = blockIdx.z;
    int tid = threadIdx.x;
    int wid = tid >> 5, lane = tid & 31;
    int gid = lane >> 2, tig = lane & 3;
    int r0 = wid * 16;
    int hkv = h >> 2;

    const __half* qbase = g_qh + ((size_t)(b*NH   + h  )) * SEQ * HD;
    const __half* kbase = g_kh + ((size_t)(b*NHKV + hkv)) * SEQ * HD;
    const __half* vtb   = g_vt + ((size_t)(b*NHKV + hkv)) * HD * SEQ;

    // ---- stage Q: 128 rows x 64 halves; 2 threads per row
    {
        int srow  = tid >> 1;
        int shalf = tid & 1;
        const uint4* qr = (const uint4*)(qbase + (size_t)(qb*128 + srow) * HD + shalf*32);
#pragma unroll
        for (int i = 0; i < 4; i++)
            *(uint4*)&APS(srow, shalf*16 + i*4) = qr[i];
    }
    __syncthreads();

    uint32_t qf[4][4];
#pragma unroll
    for (int ks = 0; ks < 4; ks++) {
        qf[ks][0] = APS(r0+gid,   ks*8+tig);
        qf[ks][1] = APS(r0+gid+8, ks*8+tig);
        qf[ks][2] = APS(r0+gid,   ks*8+tig+4);
        qf[ks][3] = APS(r0+gid+8, ks*8+tig+4);
    }

    float m0 = -1e30f, m1 = -1e30f, l0 = 0.f, l1 = 0.f;
    float o[8][4];
#pragma unroll
    for (int nt = 0; nt < 8; nt++)
#pragma unroll
        for (int j = 0; j < 4; j++) o[nt][j] = 0.f;

    int row0 = qb*128 + r0 + gid;
    int row1 = row0 + 8;
    int rowmax = qb*128 + r0 + 15;    // last q row owned by this warp

    int skey  = tid >> 2;             // 0..63
    int squar = tid & 3;              // quarter of a 64-half row

    int ntiles = 2*qb + 2;
    for (int kt = 0; kt < ntiles; kt++) {
        int k0 = kt * 64;
        __syncthreads();
        {   // stage K [key][dim] and V^T [dim][key]; 4 threads/row, 2 uint4 each
            const uint4* kr = (const uint4*)(kbase + (size_t)(k0 + skey) * HD + squar*16);
            const uint4* vr = (const uint4*)(vtb + (size_t)skey * SEQ + k0 + squar*16);
            *(uint4*)&AKS(skey, squar*8    ) = kr[0];
            *(uint4*)&AKS(skey, squar*8 + 4) = kr[1];
            *(uint4*)&AVS(skey, squar*8    ) = vr[0];
            *(uint4*)&AVS(skey, squar*8 + 4) = vr[1];
        }
        __syncthreads();

        if (k0 > rowmax) continue;     // tile fully masked for this warp

        // ---- scores S = Q @ K^T
        float s[8][4];
#pragma unroll
        for (int nt = 0; nt < 8; nt++)
#pragma unroll
            for (int j = 0; j < 4; j++) s[nt][j] = 0.f;

#pragma unroll
        for (int ks = 0; ks < 4; ks++) {
#pragma unroll
            for (int nt = 0; nt < 8; nt++) {
                uint32_t b0 = AKS(nt*8+gid, ks*8+tig);
                uint32_t b1 = AKS(nt*8+gid, ks*8+tig+4);
                mma_f16(s[nt][0], s[nt][1], s[nt][2], s[nt][3],
                        qf[ks][0], qf[ks][1], qf[ks][2], qf[ks][3], b0, b1);
            }
        }

        if (k0 + 63 > row0) {          // diagonal tile for these rows
#pragma unroll
            for (int nt = 0; nt < 8; nt++) {
                int key = k0 + nt*8 + 2*tig;
                if (key     > row0) s[nt][0] = -1e30f;
                if (key + 1 > row0) s[nt][1] = -1e30f;
                if (key     > row1) s[nt][2] = -1e30f;
                if (key + 1 > row1) s[nt][3] = -1e30f;
            }
        }

        float mx0 = m0, mx1 = m1;
#pragma unroll
        for (int nt = 0; nt < 8; nt++) {
            mx0 = fmaxf(mx0, fmaxf(s[nt][0], s[nt][1]));
            mx1 = fmaxf(mx1, fmaxf(s[nt][2], s[nt][3]));
        }
        mx0 = fmaxf(mx0, __shfl_xor_sync(0xffffffffu, mx0, 1));
        mx0 = fmaxf(mx0, __shfl_xor_sync(0xffffffffu, mx0, 2));
        mx1 = fmaxf(mx1, __shfl_xor_sync(0xffffffffu, mx1, 1));
        mx1 = fmaxf(mx1, __shfl_xor_sync(0xffffffffu, mx1, 2));

        float c0 = __expf(m0 - mx0);
        float c1 = __expf(m1 - mx1);
        m0 = mx0; m1 = mx1;
        l0 *= c0;  l1 *= c1;
#pragma unroll
        for (int nt = 0; nt < 8; nt++) {
            o[nt][0] *= c0; o[nt][1] *= c0;
            o[nt][2] *= c1; o[nt][3] *= c1;
        }

        float ps0 = 0.f, ps1 = 0.f;
#pragma unroll
        for (int nt = 0; nt < 8; nt++) {
            s[nt][0] = __expf(s[nt][0] - mx0);
            s[nt][1] = __expf(s[nt][1] - mx0);
            s[nt][2] = __expf(s[nt][2] - mx1);
            s[nt][3] = __expf(s[nt][3] - mx1);
            ps0 += s[nt][0] + s[nt][1];
            ps1 += s[nt][2] + s[nt][3];
        }
        ps0 += __shfl_xor_sync(0xffffffffu, ps0, 1);
        ps0 += __shfl_xor_sync(0xffffffffu, ps0, 2);
        ps1 += __shfl_xor_sync(0xffffffffu, ps1, 1);
        ps1 += __shfl_xor_sync(0xffffffffu, ps1, 2);
        l0 += ps0; l1 += ps1;

        // ---- P -> smem as half2 (warp-private rows)
#pragma unroll
        for (int nt = 0; nt < 8; nt++) {
            APS(r0+gid,   nt*4+tig) = f2h2(s[nt][0], s[nt][1]);
            APS(r0+gid+8, nt*4+tig) = f2h2(s[nt][2], s[nt][3]);
        }
        __syncwarp();

        // ---- O += P @ V
#pragma unroll
        for (int ks = 0; ks < 4; ks++) {
            uint32_t a0 = APS(r0+gid,   ks*8+tig);
            uint32_t a1 = APS(r0+gid+8, ks*8+tig);
            uint32_t a2 = APS(r0+gid,   ks*8+tig+4);
            uint32_t a3 = APS(r0+gid+8, ks*8+tig+4);
#pragma unroll
            for (int nt = 0; nt < 8; nt++) {
                uint32_t b0 = AVS(nt*8+gid, ks*8+tig);
                uint32_t b1 = AVS(nt*8+gid, ks*8+tig+4);
                mma_f16(o[nt][0], o[nt][1], o[nt][2], o[nt][3],
                        a0, a1, a2, a3, b0, b1);
            }
        }
    }

    // ---- finalize
    float i0 = 1.0f / l0, i1 = 1.0f / l1;
    uint32_t* y0 = g_y + (((size_t)(b*SEQ + row0)) * NH + h) * (HD/2);
    uint32_t* y1 = g_y + (((size_t)(b*SEQ + row1)) * NH + h) * (HD/2);
#pragma unroll
    for (int nt = 0; nt < 8; nt++) {
        y0[nt*4+tig] = f2h2(o[nt][0] * i0, o[nt][1] * i0);
        y1[nt*4+tig] = f2h2(o[nt][2] * i1, o[nt][3] * i1);
    }
}

// ---------------- launch ----------------------------------------------------
extern "C" void kernel_launch(void* const* d_in, const int* in_sizes, int n_in,
                              void* d_out, int out_size)
{
    const float* x  = (const float*)d_in[0];
    const float* wq = (const float*)d_in[1];
    const float* wk = (const float*)d_in[2];
    const float* wv = (const float*)d_in[3];
    const float* wo = (const float*)d_in[4];
    float* out = (float*)d_out;

    uint32_t *xh, *wqkvT, *woT, *yy;
    float *qkv;
    cudaGetSymbolAddress((void**)&xh,    g_xh);
    cudaGetSymbolAddress((void**)&qkv,   g_qkv);
    cudaGetSymbolAddress((void**)&wqkvT, g_wqkvT);
    cudaGetSymbolAddress((void**)&woT,   g_woT);
    cudaGetSymbolAddress((void**)&yy,    g_y);

    cudaFuncSetAttribute(mma_gemm_kernel, cudaFuncAttributeMaxDynamicSharedMemorySize, GEMM_SMEM);
    cudaFuncSetAttribute(attn_mma_kernel, cudaFuncAttributeMaxDynamicSharedMemorySize, ATTN_SMEM);

    // x -> half
    xconv_kernel<<<TOK*CDIM/(256*4), 256>>>(x);

    // weight transposes -> [N,K] half (qkv fused)
    transpose_kernel<<<dim3(32,32), dim3(32,8)>>>(wq, (__half*)wqkvT,               CDIM, CDIM);
    transpose_kernel<<<dim3(8, 32), dim3(32,8)>>>(wk, (__half*)(wqkvT + 1024*GKW),  CDIM, NHKV*HD);
    transpose_kernel<<<dim3(8, 32), dim3(32,8)>>>(wv, (__half*)(wqkvT + 1280*GKW),  CDIM, NHKV*HD);
    transpose_kernel<<<dim3(32,32), dim3(32,8)>>>(wo, (__half*)woT,                 CDIM, CDIM);

    // fused QKV projection
    mma_gemm_kernel<<<dim3(NQKV/128, TOK/128), 256, GEMM_SMEM>>>(xh, wqkvT, qkv, NQKV);

    // RMSNorm + RoPE (q,k) ; V transpose (coalesced)
    pack_kernel<<<(TOK*20)/8, 256>>>();
    vtrans_kernel<<<dim3(SEQ/32, HD/32, BATCH*NHKV), dim3(32,8)>>>();

    // causal SDPA (fp16 tensor cores)
    attn_mma_kernel<<<dim3(SEQ/128, NH, BATCH), 256, ATTN_SMEM>>>();

    // output projection
    mma_gemm_kernel<<<dim3(CDIM/128, TOK/128), 256, GEMM_SMEM>>>(yy, woT, out, CDIM);
}

// round 8
// speedup vs baseline: 8.0752x; 1.0142x over previous
#include <cuda_runtime.h>
#include <cuda_fp16.h>
#include <math.h>
#include <stdint.h>

// ---------------- problem constants ----------------
#define BATCH 4
#define SEQ   2048
#define CDIM  1024
#define NH    16
#define NHKV  4
#define HD    64
#define TOK   (BATCH*SEQ)          // 8192
#define GKW   512                  // K dim in half2 words (1024 halves)
#define NQKV  1536                 // 1024 + 256 + 256

// ---------------- scratch (device globals) ----------------
__device__ uint32_t g_xh  [TOK*GKW];         // x as half2 words
__device__ float    g_qkv [TOK*NQKV];        // fused qkv projection (fp32)
__device__ __half   g_qh [BATCH*NH*SEQ*HD];  // q half, scale folded (1.5/8)
__device__ __half   g_kh [BATCH*NHKV*SEQ*HD];// k half [b,hkv][n][d]
__device__ __half   g_vt [BATCH*NHKV*HD*SEQ];// v half transposed [b,hkv][d][n]
__device__ uint32_t g_y  [TOK*GKW];          // attention out, half2 words
__device__ uint32_t g_wqkvT[NQKV*GKW];       // [N,K] transposed weights half2
__device__ uint32_t g_woT  [CDIM*GKW];

// ---------------- helpers ----------------
__device__ __forceinline__ uint32_t smem_u32(const void* p) {
    uint32_t a;
    asm("{ .reg .u64 t; cvta.to.shared.u64 t, %1; cvt.u32.u64 %0, t; }" : "=r"(a) : "l"(p));
    return a;
}
__device__ __forceinline__ uint32_t f2h2(float lo, float hi) {
    __half2 h = __floats2half2_rn(lo, hi);
    return *(uint32_t*)&h;
}
__device__ __forceinline__ void mma_f16(float& d0, float& d1, float& d2, float& d3,
                                        uint32_t a0, uint32_t a1, uint32_t a2, uint32_t a3,
                                        uint32_t b0, uint32_t b1) {
    asm volatile(
        "mma.sync.aligned.m16n8k16.row.col.f32.f16.f16.f32 "
        "{%0,%1,%2,%3}, {%4,%5,%6,%7}, {%8,%9}, {%0,%1,%2,%3};"
        : "+f"(d0), "+f"(d1), "+f"(d2), "+f"(d3)
        : "r"(a0), "r"(a1), "r"(a2), "r"(a3), "r"(b0), "r"(b1));
}
#define CP_ASYNC16(saddr, gptr) \
    asm volatile("cp.async.cg.shared.global [%0], [%1], 16;" :: "r"(saddr), "l"(gptr))
#define CP_COMMIT()  asm volatile("cp.async.commit_group;" ::: "memory")
#define CP_WAIT(n)   asm volatile("cp.async.wait_group %0;" :: "n"(n) : "memory")

// ---------------- x -> half2 words -----------------------------------------
__global__ __launch_bounds__(256) void xconv_kernel(const float* __restrict__ x)
{
    int i = (blockIdx.x * 256 + threadIdx.x) * 4;
    float4 f = *(const float4*)(x + i);
    uint2 u;
    u.x = f2h2(f.x, f.y);
    u.y = f2h2(f.z, f.w);
    *(uint2*)(g_xh + i/2) = u;
}

// ---------------- weight transpose (+half): D[c][r] = h(S[r][c]) -----------
__global__ __launch_bounds__(256) void transpose_kernel(
    const float* __restrict__ S, __half* __restrict__ D, int R, int Ccols)
{
    __shared__ float t[32][33];
    int bx = blockIdx.x * 32, by = blockIdx.y * 32;
#pragma unroll
    for (int i = 0; i < 32; i += 8)
        t[threadIdx.y + i][threadIdx.x] = S[(size_t)(by + threadIdx.y + i) * Ccols + bx + threadIdx.x];
    __syncthreads();
#pragma unroll
    for (int i = 0; i < 32; i += 8)
        D[(size_t)(bx + threadIdx.y + i) * R + by + threadIdx.x] = __float2half(t[threadIdx.x][threadIdx.y + i]);
}

// ---------------- fp16 GEMM, 2-stage double buffer, 2 CTAs/SM ---------------
#define GS   2
#define GBK  32
#define GSTR 36
#define STAGE_W (128*GSTR)
#define GEMM_SMEM (2*GS*STAGE_W*4)     // 73728 B

__global__ __launch_bounds__(256, 2) void mma_gemm_kernel(
    const uint32_t* __restrict__ A, const uint32_t* __restrict__ Bt,
    float* __restrict__ C, int Np)
{
    extern __shared__ uint32_t gsm[];
    uint32_t* As = gsm;
    uint32_t* Bs = gsm + GS*STAGE_W;

    int tid  = threadIdx.x;
    int wid  = tid >> 5, lane = tid & 31;
    int gid  = lane >> 2, tig = lane & 3;
    int wm   = (wid & 1) * 64;
    int wn   = (wid >> 1) * 32;

    int lr = tid >> 1;
    int lc = (tid & 1) * 16;

    const uint32_t* Ag = A  + (size_t)blockIdx.y * 128 * GKW + (size_t)lr * GKW + lc;
    const uint32_t* Bg = Bt + (size_t)blockIdx.x * 128 * GKW + (size_t)lr * GKW + lc;

    uint32_t sA = smem_u32(As) + (uint32_t)(lr * GSTR + lc) * 4u;
    uint32_t sB = smem_u32(Bs) + (uint32_t)(lr * GSTR + lc) * 4u;
    const uint32_t stageB = STAGE_W * 4u;

    float acc[4][4][4];
#pragma unroll
    for (int i = 0; i < 4; i++)
#pragma unroll
        for (int j = 0; j < 4; j++)
#pragma unroll
            for (int r = 0; r < 4; r++) acc[i][j][r] = 0.f;

    const int NIT = GKW / GBK;     // 16

    // prologue: chunk 0 into buf 0
#pragma unroll
    for (int i = 0; i < 4; i++) {
        CP_ASYNC16(sA + i*16, Ag + i*4);
        CP_ASYNC16(sB + i*16, Bg + i*4);
    }
    CP_COMMIT();

    for (int c = 0; c < NIT; c++) {
        int buf = c & 1;
        if (c + 1 < NIT) {
            int nb = buf ^ 1;
#pragma unroll
            for (int i = 0; i < 4; i++) {
                CP_ASYNC16(sA + nb*stageB + i*16, Ag + (c+1)*GBK + i*4);
                CP_ASYNC16(sB + nb*stageB + i*16, Bg + (c+1)*GBK + i*4);
            }
            CP_COMMIT();
            CP_WAIT(1);            // chunk c complete, c+1 in flight
        } else {
            CP_WAIT(0);            // tail: wait everything
        }
        __syncthreads();

        const uint32_t* Ab_ = As + buf * STAGE_W;
        const uint32_t* Bb_ = Bs + buf * STAGE_W;

#pragma unroll
        for (int kk = 0; kk < 4; kk++) {
            int kb = kk * 8;
            uint32_t af[4][4], bf[4][2];
#pragma unroll
            for (int mt = 0; mt < 4; mt++) {
                int r0 = (wm + mt*16 + gid) * GSTR;
                af[mt][0] = Ab_[r0          + kb + tig];
                af[mt][1] = Ab_[r0 + 8*GSTR + kb + tig];
                af[mt][2] = Ab_[r0          + kb + tig + 4];
                af[mt][3] = Ab_[r0 + 8*GSTR + kb + tig + 4];
            }
#pragma unroll
            for (int nt = 0; nt < 4; nt++) {
                int n0 = (wn + nt*8 + gid) * GSTR;
                bf[nt][0] = Bb_[n0 + kb + tig];
                bf[nt][1] = Bb_[n0 + kb + tig + 4];
            }
#pragma unroll
            for (int mt = 0; mt < 4; mt++)
#pragma unroll
                for (int nt = 0; nt < 4; nt++)
                    mma_f16(acc[mt][nt][0], acc[mt][nt][1], acc[mt][nt][2], acc[mt][nt][3],
                            af[mt][0], af[mt][1], af[mt][2], af[mt][3],
                            bf[nt][0], bf[nt][1]);
        }
        __syncthreads();           // protect buf before next-next issue
    }

    int baseRow = blockIdx.y * 128 + wm;
    int baseCol = blockIdx.x * 128 + wn;
#pragma unroll
    for (int mt = 0; mt < 4; mt++) {
#pragma unroll
        for (int nt = 0; nt < 4; nt++) {
            int row = baseRow + mt * 16 + gid;
            int col = baseCol + nt * 8 + tig * 2;
            *(float2*)(C + (size_t)row * Np + col)       = make_float2(acc[mt][nt][0], acc[mt][nt][1]);
            *(float2*)(C + (size_t)(row + 8) * Np + col) = make_float2(acc[mt][nt][2], acc[mt][nt][3]);
        }
    }
}

// ---------------- pack: RMSNorm + RoPE (+gain) for q/k only ----------------
__global__ __launch_bounds__(256) void pack_kernel()
{
    int w    = (blockIdx.x * 256 + threadIdx.x) >> 5;
    int lane = threadIdx.x & 31;
    int t    = w / 20;
    int slot = w - t * 20;
    int b = t / SEQ;
    int n = t - b * SEQ;

    float v0, v1;
    float gain;
    __half* dst;

    if (slot < 16) {
        const float* src = g_qkv + (size_t)t * NQKV + slot * HD;
        v0 = src[lane]; v1 = src[lane + 32];
        dst = g_qh + (((size_t)(b * NH + slot)) * SEQ + n) * HD;
        gain = 1.5f * 0.125f;
    } else {
        int h = slot - 16;
        const float* src = g_qkv + (size_t)t * NQKV + 1024 + h * HD;
        v0 = src[lane]; v1 = src[lane + 32];
        dst = g_kh + (((size_t)(b * NHKV + h)) * SEQ + n) * HD;
        gain = 1.0f;
    }

    float ss = v0*v0 + v1*v1;
#pragma unroll
    for (int o = 16; o; o >>= 1) ss += __shfl_xor_sync(0xffffffffu, ss, o);
    float r = rsqrtf(ss * (1.0f/64.0f) + 1.1920929e-7f);
    v0 *= r; v1 *= r;
    float inv_freq = powf(10000.0f, -(float)lane * (1.0f/32.0f));
    float ang = (float)n * inv_freq;
    float sv, cv;
    sincosf(ang, &sv, &cv);
    float o0 = v0*cv - v1*sv;
    float o1 = v1*cv + v0*sv;
    dst[lane]      = __float2half(o0 * gain);
    dst[lane + 32] = __float2half(o1 * gain);
}

// ---------------- V transpose: g_qkv v-section -> g_vt [b,h][d][n] ----------
__global__ __launch_bounds__(256) void vtrans_kernel()
{
    __shared__ float t[32][33];
    int z  = blockIdx.z;
    int d0 = blockIdx.y * 32;
    int n0 = blockIdx.x * 32;
    int b  = z >> 2, h = z & 3;
    int tx = threadIdx.x, ty = threadIdx.y;

    const float* src = g_qkv + 1280 + h * HD + d0 + tx;
#pragma unroll
    for (int i = 0; i < 32; i += 8)
        t[ty + i][tx] = src[(size_t)(b*SEQ + n0 + ty + i) * NQKV];
    __syncthreads();

    __half* dst = g_vt + (size_t)z * HD * SEQ + n0 + tx;
#pragma unroll
    for (int i = 0; i < 32; i += 8)
        dst[(size_t)(d0 + ty + i) * SEQ] = __float2half(t[tx][ty + i]);
}

// ---------------- fp16 tensor-core causal flash attention -------------------
#define ASTR 36
#define AKS(k,wd) smA[(k)*ASTR + (wd)]
#define AVS(d,wd) smA[64*ASTR + (d)*ASTR + (wd)]
#define APS(r,wd) smA[128*ASTR + (r)*ASTR + (wd)]
#define ATTN_SMEM (256*ASTR*4)

__global__ __launch_bounds__(256) void attn_mma_kernel()
{
    extern __shared__ uint32_t smA[];

    int qb = blockIdx.x, h = blockIdx.y, b = blockIdx.z;
    int tid = threadIdx.x;
    int wid = tid >> 5, lane = tid & 31;
    int gid = lane >> 2, tig = lane & 3;
    int r0 = wid * 16;
    int hkv = h >> 2;

    const __half* qbase = g_qh + ((size_t)(b*NH   + h  )) * SEQ * HD;
    const __half* kbase = g_kh + ((size_t)(b*NHKV + hkv)) * SEQ * HD;
    const __half* vtb   = g_vt + ((size_t)(b*NHKV + hkv)) * HD * SEQ;

    {
        int srow  = tid >> 1;
        int shalf = tid & 1;
        const uint4* qr = (const uint4*)(qbase + (size_t)(qb*128 + srow) * HD + shalf*32);
#pragma unroll
        for (int i = 0; i < 4; i++)
            *(uint4*)&APS(srow, shalf*16 + i*4) = qr[i];
    }
    __syncthreads();

    uint32_t qf[4][4];
#pragma unroll
    for (int ks = 0; ks < 4; ks++) {
        qf[ks][0] = APS(r0+gid,   ks*8+tig);
        qf[ks][1] = APS(r0+gid+8, ks*8+tig);
        qf[ks][2] = APS(r0+gid,   ks*8+tig+4);
        qf[ks][3] = APS(r0+gid+8, ks*8+tig+4);
    }

    float m0 = -1e30f, m1 = -1e30f, l0 = 0.f, l1 = 0.f;
    float o[8][4];
#pragma unroll
    for (int nt = 0; nt < 8; nt++)
#pragma unroll
        for (int j = 0; j < 4; j++) o[nt][j] = 0.f;

    int row0 = qb*128 + r0 + gid;
    int row1 = row0 + 8;
    int rowmax = qb*128 + r0 + 15;

    int skey  = tid >> 2;
    int squar = tid & 3;

    int ntiles = 2*qb + 2;
    for (int kt = 0; kt < ntiles; kt++) {
        int k0 = kt * 64;
        __syncthreads();
        {
            const uint4* kr = (const uint4*)(kbase + (size_t)(k0 + skey) * HD + squar*16);
            const uint4* vr = (const uint4*)(vtb + (size_t)skey * SEQ + k0 + squar*16);
            *(uint4*)&AKS(skey, squar*8    ) = kr[0];
            *(uint4*)&AKS(skey, squar*8 + 4) = kr[1];
            *(uint4*)&AVS(skey, squar*8    ) = vr[0];
            *(uint4*)&AVS(skey, squar*8 + 4) = vr[1];
        }
        __syncthreads();

        if (k0 > rowmax) continue;

        float s[8][4];
#pragma unroll
        for (int nt = 0; nt < 8; nt++)
#pragma unroll
            for (int j = 0; j < 4; j++) s[nt][j] = 0.f;

#pragma unroll
        for (int ks = 0; ks < 4; ks++) {
#pragma unroll
            for (int nt = 0; nt < 8; nt++) {
                uint32_t b0 = AKS(nt*8+gid, ks*8+tig);
                uint32_t b1 = AKS(nt*8+gid, ks*8+tig+4);
                mma_f16(s[nt][0], s[nt][1], s[nt][2], s[nt][3],
                        qf[ks][0], qf[ks][1], qf[ks][2], qf[ks][3], b0, b1);
            }
        }

        if (k0 + 63 > row0) {
#pragma unroll
            for (int nt = 0; nt < 8; nt++) {
                int key = k0 + nt*8 + 2*tig;
                if (key     > row0) s[nt][0] = -1e30f;
                if (key + 1 > row0) s[nt][1] = -1e30f;
                if (key     > row1) s[nt][2] = -1e30f;
                if (key + 1 > row1) s[nt][3] = -1e30f;
            }
        }

        float mx0 = m0, mx1 = m1;
#pragma unroll
        for (int nt = 0; nt < 8; nt++) {
            mx0 = fmaxf(mx0, fmaxf(s[nt][0], s[nt][1]));
            mx1 = fmaxf(mx1, fmaxf(s[nt][2], s[nt][3]));
        }
        mx0 = fmaxf(mx0, __shfl_xor_sync(0xffffffffu, mx0, 1));
        mx0 = fmaxf(mx0, __shfl_xor_sync(0xffffffffu, mx0, 2));
        mx1 = fmaxf(mx1, __shfl_xor_sync(0xffffffffu, mx1, 1));
        mx1 = fmaxf(mx1, __shfl_xor_sync(0xffffffffu, mx1, 2));

        float c0 = __expf(m0 - mx0);
        float c1 = __expf(m1 - mx1);
        m0 = mx0; m1 = mx1;
        l0 *= c0;  l1 *= c1;
#pragma unroll
        for (int nt = 0; nt < 8; nt++) {
            o[nt][0] *= c0; o[nt][1] *= c0;
            o[nt][2] *= c1; o[nt][3] *= c1;
        }

        float ps0 = 0.f, ps1 = 0.f;
#pragma unroll
        for (int nt = 0; nt < 8; nt++) {
            s[nt][0] = __expf(s[nt][0] - mx0);
            s[nt][1] = __expf(s[nt][1] - mx0);
            s[nt][2] = __expf(s[nt][2] - mx1);
            s[nt][3] = __expf(s[nt][3] - mx1);
            ps0 += s[nt][0] + s[nt][1];
            ps1 += s[nt][2] + s[nt][3];
        }
        ps0 += __shfl_xor_sync(0xffffffffu, ps0, 1);
        ps0 += __shfl_xor_sync(0xffffffffu, ps0, 2);
        ps1 += __shfl_xor_sync(0xffffffffu, ps1, 1);
        ps1 += __shfl_xor_sync(0xffffffffu, ps1, 2);
        l0 += ps0; l1 += ps1;

#pragma unroll
        for (int nt = 0; nt < 8; nt++) {
            APS(r0+gid,   nt*4+tig) = f2h2(s[nt][0], s[nt][1]);
            APS(r0+gid+8, nt*4+tig) = f2h2(s[nt][2], s[nt][3]);
        }
        __syncwarp();

#pragma unroll
        for (int ks = 0; ks < 4; ks++) {
            uint32_t a0 = APS(r0+gid,   ks*8+tig);
            uint32_t a1 = APS(r0+gid+8, ks*8+tig);
            uint32_t a2 = APS(r0+gid,   ks*8+tig+4);
            uint32_t a3 = APS(r0+gid+8, ks*8+tig+4);
#pragma unroll
            for (int nt = 0; nt < 8; nt++) {
                uint32_t b0 = AVS(nt*8+gid, ks*8+tig);
                uint32_t b1 = AVS(nt*8+gid, ks*8+tig+4);
                mma_f16(o[nt][0], o[nt][1], o[nt][2], o[nt][3],
                        a0, a1, a2, a3, b0, b1);
            }
        }
    }

    float i0 = 1.0f / l0, i1 = 1.0f / l1;
    uint32_t* y0 = g_y + (((size_t)(b*SEQ + row0)) * NH + h) * (HD/2);
    uint32_t* y1 = g_y + (((size_t)(b*SEQ + row1)) * NH + h) * (HD/2);
#pragma unroll
    for (int nt = 0; nt < 8; nt++) {
        y0[nt*4+tig] = f2h2(o[nt][0] * i0, o[nt][1] * i0);
        y1[nt*4+tig] = f2h2(o[nt][2] * i1, o[nt][3] * i1);
    }
}

// ---------------- launch ----------------------------------------------------
extern "C" void kernel_launch(void* const* d_in, const int* in_sizes, int n_in,
                              void* d_out, int out_size)
{
    const float* x  = (const float*)d_in[0];
    const float* wq = (const float*)d_in[1];
    const float* wk = (const float*)d_in[2];
    const float* wv = (const float*)d_in[3];
    const float* wo = (const float*)d_in[4];
    float* out = (float*)d_out;

    uint32_t *xh, *wqkvT, *woT, *yy;
    float *qkv;
    cudaGetSymbolAddress((void**)&xh,    g_xh);
    cudaGetSymbolAddress((void**)&qkv,   g_qkv);
    cudaGetSymbolAddress((void**)&wqkvT, g_wqkvT);
    cudaGetSymbolAddress((void**)&woT,   g_woT);
    cudaGetSymbolAddress((void**)&yy,    g_y);

    static bool init_done = false;
    static cudaStream_t s1;
    static cudaEvent_t e_fork, e_wt, e_wo;
    if (!init_done) {
        cudaStreamCreateWithFlags(&s1, cudaStreamNonBlocking);
        cudaEventCreateWithFlags(&e_fork, cudaEventDisableTiming);
        cudaEventCreateWithFlags(&e_wt,   cudaEventDisableTiming);
        cudaEventCreateWithFlags(&e_wo,   cudaEventDisableTiming);
        cudaFuncSetAttribute(mma_gemm_kernel, cudaFuncAttributeMaxDynamicSharedMemorySize, GEMM_SMEM);
        cudaFuncSetAttribute(attn_mma_kernel, cudaFuncAttributeMaxDynamicSharedMemorySize, ATTN_SMEM);
        init_done = true;
    }

    // fork side stream for weight transposes
    cudaEventRecord(e_fork, 0);
    cudaStreamWaitEvent(s1, e_fork, 0);

    // main stream: x conversion (overlaps with transposes on s1)
    xconv_kernel<<<TOK*CDIM/(256*4), 256>>>(x);

    // side stream: qkv weight transposes, then wo transpose
    transpose_kernel<<<dim3(32,32), dim3(32,8), 0, s1>>>(wq, (__half*)wqkvT,               CDIM, CDIM);
    transpose_kernel<<<dim3(8, 32), dim3(32,8), 0, s1>>>(wk, (__half*)(wqkvT + 1024*GKW),  CDIM, NHKV*HD);
    transpose_kernel<<<dim3(8, 32), dim3(32,8), 0, s1>>>(wv, (__half*)(wqkvT + 1280*GKW),  CDIM, NHKV*HD);
    cudaEventRecord(e_wt, s1);
    transpose_kernel<<<dim3(32,32), dim3(32,8), 0, s1>>>(wo, (__half*)woT,                 CDIM, CDIM);
    cudaEventRecord(e_wo, s1);

    // main stream waits for qkv weights only
    cudaStreamWaitEvent(0, e_wt, 0);

    // fused QKV projection
    mma_gemm_kernel<<<dim3(NQKV/128, TOK/128), 256, GEMM_SMEM>>>(xh, wqkvT, qkv, NQKV);

    // RMSNorm + RoPE (q,k) ; V transpose
    pack_kernel<<<(TOK*20)/8, 256>>>();
    vtrans_kernel<<<dim3(SEQ/32, HD/32, BATCH*NHKV), dim3(32,8)>>>();

    // causal SDPA (fp16 tensor cores)
    attn_mma_kernel<<<dim3(SEQ/128, NH, BATCH), 256, ATTN_SMEM>>>();

    // output projection (needs woT)
    cudaStreamWaitEvent(0, e_wo, 0);
    mma_gemm_kernel<<<dim3(CDIM/128, TOK/128), 256, GEMM_SMEM>>>(yy, woT, out, CDIM);
}

// round 9
// speedup vs baseline: 8.2615x; 1.0231x over previous
#include <cuda_runtime.h>
#include <cuda_fp16.h>
#include <math.h>
#include <stdint.h>

// ---------------- problem constants ----------------
#define BATCH 4
#define SEQ   2048
#define CDIM  1024
#define NH    16
#define NHKV  4
#define HD    64
#define TOK   (BATCH*SEQ)          // 8192
#define GKW   512                  // K dim in half2 words (1024 halves)
#define NQKV  1536                 // 1024 + 256 + 256

// ---------------- scratch (device globals) ----------------
__device__ uint32_t g_xh  [TOK*GKW];         // x as half2 words
__device__ float    g_qkv [TOK*NQKV];        // fused qkv projection (fp32)
__device__ __half   g_qh [BATCH*NH*SEQ*HD];  // q half, scale folded (1.5/8)
__device__ __half   g_kh [BATCH*NHKV*SEQ*HD];// k half [b,hkv][n][d]
__device__ __half   g_vt [BATCH*NHKV*HD*SEQ];// v half transposed [b,hkv][d][n]
__device__ uint32_t g_y  [TOK*GKW];          // attention out, half2 words
__device__ uint32_t g_wqkvT[NQKV*GKW];       // [N,K] transposed weights half2
__device__ uint32_t g_woT  [CDIM*GKW];

// ---------------- helpers ----------------
__device__ __forceinline__ uint32_t smem_u32(const void* p) {
    uint32_t a;
    asm("{ .reg .u64 t; cvta.to.shared.u64 t, %1; cvt.u32.u64 %0, t; }" : "=r"(a) : "l"(p));
    return a;
}
__device__ __forceinline__ uint32_t f2h2(float lo, float hi) {
    __half2 h = __floats2half2_rn(lo, hi);
    return *(uint32_t*)&h;
}
__device__ __forceinline__ void mma_f16(float& d0, float& d1, float& d2, float& d3,
                                        uint32_t a0, uint32_t a1, uint32_t a2, uint32_t a3,
                                        uint32_t b0, uint32_t b1) {
    asm volatile(
        "mma.sync.aligned.m16n8k16.row.col.f32.f16.f16.f32 "
        "{%0,%1,%2,%3}, {%4,%5,%6,%7}, {%8,%9}, {%0,%1,%2,%3};"
        : "+f"(d0), "+f"(d1), "+f"(d2), "+f"(d3)
        : "r"(a0), "r"(a1), "r"(a2), "r"(a3), "r"(b0), "r"(b1));
}
#define CP_ASYNC16(saddr, gptr) \
    asm volatile("cp.async.cg.shared.global [%0], [%1], 16;" :: "r"(saddr), "l"(gptr))
#define CP_COMMIT()  asm volatile("cp.async.commit_group;" ::: "memory")
#define CP_WAIT(n)   asm volatile("cp.async.wait_group %0;" :: "n"(n) : "memory")

// ---------------- x -> half2 words -----------------------------------------
__global__ __launch_bounds__(256) void xconv_kernel(const float* __restrict__ x)
{
    int i = (blockIdx.x * 256 + threadIdx.x) * 4;
    float4 f = *(const float4*)(x + i);
    uint2 u;
    u.x = f2h2(f.x, f.y);
    u.y = f2h2(f.z, f.w);
    *(uint2*)(g_xh + i/2) = u;
}

// ---------------- weight transpose (+half): D[c][r] = h(S[r][c]) -----------
__global__ __launch_bounds__(256) void transpose_kernel(
    const float* __restrict__ S, __half* __restrict__ D, int R, int Ccols)
{
    __shared__ float t[32][33];
    int bx = blockIdx.x * 32, by = blockIdx.y * 32;
#pragma unroll
    for (int i = 0; i < 32; i += 8)
        t[threadIdx.y + i][threadIdx.x] = S[(size_t)(by + threadIdx.y + i) * Ccols + bx + threadIdx.x];
    __syncthreads();
#pragma unroll
    for (int i = 0; i < 32; i += 8)
        D[(size_t)(bx + threadIdx.y + i) * R + by + threadIdx.x] = __float2half(t[threadIdx.x][threadIdx.y + i]);
}

// ---------------- fp16 GEMM, 2-stage double buffer ---------------
#define GS   2
#define GBK  32
#define GSTR 36
#define STAGE_W (128*GSTR)
#define GEMM_SMEM (2*GS*STAGE_W*4)     // 73728 B

__global__ __launch_bounds__(256, 2) void mma_gemm_kernel(
    const uint32_t* __restrict__ A, const uint32_t* __restrict__ Bt,
    float* __restrict__ C, int Np)
{
    extern __shared__ uint32_t gsm[];
    uint32_t* As = gsm;
    uint32_t* Bs = gsm + GS*STAGE_W;

    int tid  = threadIdx.x;
    int wid  = tid >> 5, lane = tid & 31;
    int gid  = lane >> 2, tig = lane & 3;
    int wm   = (wid & 1) * 64;
    int wn   = (wid >> 1) * 32;

    int lr = tid >> 1;
    int lc = (tid & 1) * 16;

    const uint32_t* Ag = A  + (size_t)blockIdx.y * 128 * GKW + (size_t)lr * GKW + lc;
    const uint32_t* Bg = Bt + (size_t)blockIdx.x * 128 * GKW + (size_t)lr * GKW + lc;

    uint32_t sA = smem_u32(As) + (uint32_t)(lr * GSTR + lc) * 4u;
    uint32_t sB = smem_u32(Bs) + (uint32_t)(lr * GSTR + lc) * 4u;
    const uint32_t stageB = STAGE_W * 4u;

    float acc[4][4][4];
#pragma unroll
    for (int i = 0; i < 4; i++)
#pragma unroll
        for (int j = 0; j < 4; j++)
#pragma unroll
            for (int r = 0; r < 4; r++) acc[i][j][r] = 0.f;

    const int NIT = GKW / GBK;     // 16

#pragma unroll
    for (int i = 0; i < 4; i++) {
        CP_ASYNC16(sA + i*16, Ag + i*4);
        CP_ASYNC16(sB + i*16, Bg + i*4);
    }
    CP_COMMIT();

    for (int c = 0; c < NIT; c++) {
        int buf = c & 1;
        if (c + 1 < NIT) {
            int nb = buf ^ 1;
#pragma unroll
            for (int i = 0; i < 4; i++) {
                CP_ASYNC16(sA + nb*stageB + i*16, Ag + (c+1)*GBK + i*4);
                CP_ASYNC16(sB + nb*stageB + i*16, Bg + (c+1)*GBK + i*4);
            }
            CP_COMMIT();
            CP_WAIT(1);
        } else {
            CP_WAIT(0);
        }
        __syncthreads();

        const uint32_t* Ab_ = As + buf * STAGE_W;
        const uint32_t* Bb_ = Bs + buf * STAGE_W;

#pragma unroll
        for (int kk = 0; kk < 4; kk++) {
            int kb = kk * 8;
            uint32_t af[4][4], bf[4][2];
#pragma unroll
            for (int mt = 0; mt < 4; mt++) {
                int r0 = (wm + mt*16 + gid) * GSTR;
                af[mt][0] = Ab_[r0          + kb + tig];
                af[mt][1] = Ab_[r0 + 8*GSTR + kb + tig];
                af[mt][2] = Ab_[r0          + kb + tig + 4];
                af[mt][3] = Ab_[r0 + 8*GSTR + kb + tig + 4];
            }
#pragma unroll
            for (int nt = 0; nt < 4; nt++) {
                int n0 = (wn + nt*8 + gid) * GSTR;
                bf[nt][0] = Bb_[n0 + kb + tig];
                bf[nt][1] = Bb_[n0 + kb + tig + 4];
            }
#pragma unroll
            for (int mt = 0; mt < 4; mt++)
#pragma unroll
                for (int nt = 0; nt < 4; nt++)
                    mma_f16(acc[mt][nt][0], acc[mt][nt][1], acc[mt][nt][2], acc[mt][nt][3],
                            af[mt][0], af[mt][1], af[mt][2], af[mt][3],
                            bf[nt][0], bf[nt][1]);
        }
        __syncthreads();
    }

    int baseRow = blockIdx.y * 128 + wm;
    int baseCol = blockIdx.x * 128 + wn;
#pragma unroll
    for (int mt = 0; mt < 4; mt++) {
#pragma unroll
        for (int nt = 0; nt < 4; nt++) {
            int row = baseRow + mt * 16 + gid;
            int col = baseCol + nt * 8 + tig * 2;
            *(float2*)(C + (size_t)row * Np + col)       = make_float2(acc[mt][nt][0], acc[mt][nt][1]);
            *(float2*)(C + (size_t)(row + 8) * Np + col) = make_float2(acc[mt][nt][2], acc[mt][nt][3]);
        }
    }
}

// ---------------- pack: RMSNorm + RoPE (+gain) for q/k only ----------------
__global__ __launch_bounds__(256) void pack_kernel()
{
    int w    = (blockIdx.x * 256 + threadIdx.x) >> 5;
    int lane = threadIdx.x & 31;
    int t    = w / 20;
    int slot = w - t * 20;
    int b = t / SEQ;
    int n = t - b * SEQ;

    float v0, v1;
    float gain;
    __half* dst;

    if (slot < 16) {
        const float* src = g_qkv + (size_t)t * NQKV + slot * HD;
        v0 = src[lane]; v1 = src[lane + 32];
        dst = g_qh + (((size_t)(b * NH + slot)) * SEQ + n) * HD;
        gain = 1.5f * 0.125f;
    } else {
        int h = slot - 16;
        const float* src = g_qkv + (size_t)t * NQKV + 1024 + h * HD;
        v0 = src[lane]; v1 = src[lane + 32];
        dst = g_kh + (((size_t)(b * NHKV + h)) * SEQ + n) * HD;
        gain = 1.0f;
    }

    float ss = v0*v0 + v1*v1;
#pragma unroll
    for (int o = 16; o; o >>= 1) ss += __shfl_xor_sync(0xffffffffu, ss, o);
    float r = rsqrtf(ss * (1.0f/64.0f) + 1.1920929e-7f);
    v0 *= r; v1 *= r;
    float inv_freq = powf(10000.0f, -(float)lane * (1.0f/32.0f));
    float ang = (float)n * inv_freq;
    float sv, cv;
    sincosf(ang, &sv, &cv);
    float o0 = v0*cv - v1*sv;
    float o1 = v1*cv + v0*sv;
    dst[lane]      = __float2half(o0 * gain);
    dst[lane + 32] = __float2half(o1 * gain);
}

// ---------------- V transpose: g_qkv v-section -> g_vt [b,h][d][n] ----------
__global__ __launch_bounds__(256) void vtrans_kernel()
{
    __shared__ float t[32][33];
    int z  = blockIdx.z;
    int d0 = blockIdx.y * 32;
    int n0 = blockIdx.x * 32;
    int b  = z >> 2, h = z & 3;
    int tx = threadIdx.x, ty = threadIdx.y;

    const float* src = g_qkv + 1280 + h * HD + d0 + tx;
#pragma unroll
    for (int i = 0; i < 32; i += 8)
        t[ty + i][tx] = src[(size_t)(b*SEQ + n0 + ty + i) * NQKV];
    __syncthreads();

    __half* dst = g_vt + (size_t)z * HD * SEQ + n0 + tx;
#pragma unroll
    for (int i = 0; i < 32; i += 8)
        dst[(size_t)(d0 + ty + i) * SEQ] = __float2half(t[tx][ty + i]);
}

// ---------------- fp16 tensor-core causal flash attention -------------------
// CTA: 128 q-rows, 8 warps x 16 rows, 64-key tiles, cp.async double-buffered
#define ASTR 36
#define KOFF(st) ((st)*64*ASTR)
#define VOFF(st) (2*64*ASTR + (st)*64*ASTR)
#define QPOFF    (4*64*ASTR)
#define AKS(st,k,wd) smA[KOFF(st) + (k)*ASTR + (wd)]
#define AVS(st,d,wd) smA[VOFF(st) + (d)*ASTR + (wd)]
#define APS(r,wd)    smA[QPOFF    + (r)*ASTR + (wd)]
#define ATTN_SMEM ((4*64 + 128)*ASTR*4)     // 55296 B

__global__ __launch_bounds__(256, 2) void attn_mma_kernel()
{
    extern __shared__ uint32_t smA[];

    int qb = blockIdx.x, h = blockIdx.y, b = blockIdx.z;
    int tid = threadIdx.x;
    int wid = tid >> 5, lane = tid & 31;
    int gid = lane >> 2, tig = lane & 3;
    int r0 = wid * 16;
    int hkv = h >> 2;

    const __half* qbase = g_qh + ((size_t)(b*NH   + h  )) * SEQ * HD;
    const __half* kbase = g_kh + ((size_t)(b*NHKV + hkv)) * SEQ * HD;
    const __half* vtb   = g_vt + ((size_t)(b*NHKV + hkv)) * HD * SEQ;

    int skey  = tid >> 2;             // 0..63
    int squar = tid & 3;              // quarter of a 64-half row

    uint32_t smbase = smem_u32(smA);
    uint32_t kdst0 = smbase + (uint32_t)(skey*ASTR + squar*8) * 4u;
    const uint32_t kstage = (uint32_t)(64*ASTR) * 4u;

    int ntiles = 2*qb + 2;

    // ---- prologue: issue tile 0 K/V via cp.async
    {
        const __half* kr = kbase + (size_t)skey * HD + squar*16;
        const __half* vr = vtb + (size_t)skey * SEQ + squar*16;
        CP_ASYNC16(kdst0,                         kr);
        CP_ASYNC16(kdst0 + 16,                    kr + 8);
        CP_ASYNC16(kdst0 + 2*kstage,              vr);
        CP_ASYNC16(kdst0 + 2*kstage + 16,         vr + 8);
        CP_COMMIT();
    }

    // ---- stage Q: 128 rows x 64 halves; 2 threads per row
    {
        int srow  = tid >> 1;
        int shalf = tid & 1;
        const uint4* qr = (const uint4*)(qbase + (size_t)(qb*128 + srow) * HD + shalf*32);
#pragma unroll
        for (int i = 0; i < 4; i++)
            *(uint4*)&APS(srow, shalf*16 + i*4) = qr[i];
    }
    __syncthreads();

    uint32_t qf[4][4];
#pragma unroll
    for (int ks = 0; ks < 4; ks++) {
        qf[ks][0] = APS(r0+gid,   ks*8+tig);
        qf[ks][1] = APS(r0+gid+8, ks*8+tig);
        qf[ks][2] = APS(r0+gid,   ks*8+tig+4);
        qf[ks][3] = APS(r0+gid+8, ks*8+tig+4);
    }

    float m0 = -1e30f, m1 = -1e30f, l0 = 0.f, l1 = 0.f;
    float o[8][4];
#pragma unroll
    for (int nt = 0; nt < 8; nt++)
#pragma unroll
        for (int j = 0; j < 4; j++) o[nt][j] = 0.f;

    int row0 = qb*128 + r0 + gid;
    int row1 = row0 + 8;
    int rowmax = qb*128 + r0 + 15;

    for (int kt = 0; kt < ntiles; kt++) {
        int k0 = kt * 64;
        int buf = kt & 1;

        if (kt + 1 < ntiles) {       // issue next tile (buffer protected by kt-1's trailing sync)
            int nb = buf ^ 1;
            int nk0 = k0 + 64;
            const __half* kr = kbase + (size_t)(nk0 + skey) * HD + squar*16;
            const __half* vr = vtb + (size_t)skey * SEQ + nk0 + squar*16;
            CP_ASYNC16(kdst0 + nb*kstage,                 kr);
            CP_ASYNC16(kdst0 + nb*kstage + 16,            kr + 8);
            CP_ASYNC16(kdst0 + (2+nb)*kstage,             vr);
            CP_ASYNC16(kdst0 + (2+nb)*kstage + 16,        vr + 8);
            CP_COMMIT();
            CP_WAIT(1);
        } else {
            CP_WAIT(0);
        }
        __syncthreads();

        if (k0 <= rowmax) {
            // ---- scores S = Q @ K^T
            float s[8][4];
#pragma unroll
            for (int nt = 0; nt < 8; nt++)
#pragma unroll
                for (int j = 0; j < 4; j++) s[nt][j] = 0.f;

#pragma unroll
            for (int ks = 0; ks < 4; ks++) {
#pragma unroll
                for (int nt = 0; nt < 8; nt++) {
                    uint32_t b0 = AKS(buf, nt*8+gid, ks*8+tig);
                    uint32_t b1 = AKS(buf, nt*8+gid, ks*8+tig+4);
                    mma_f16(s[nt][0], s[nt][1], s[nt][2], s[nt][3],
                            qf[ks][0], qf[ks][1], qf[ks][2], qf[ks][3], b0, b1);
                }
            }

            if (k0 + 63 > row0) {
#pragma unroll
                for (int nt = 0; nt < 8; nt++) {
                    int key = k0 + nt*8 + 2*tig;
                    if (key     > row0) s[nt][0] = -1e30f;
                    if (key + 1 > row0) s[nt][1] = -1e30f;
                    if (key     > row1) s[nt][2] = -1e30f;
                    if (key + 1 > row1) s[nt][3] = -1e30f;
                }
            }

            float mx0 = m0, mx1 = m1;
#pragma unroll
            for (int nt = 0; nt < 8; nt++) {
                mx0 = fmaxf(mx0, fmaxf(s[nt][0], s[nt][1]));
                mx1 = fmaxf(mx1, fmaxf(s[nt][2], s[nt][3]));
            }
            mx0 = fmaxf(mx0, __shfl_xor_sync(0xffffffffu, mx0, 1));
            mx0 = fmaxf(mx0, __shfl_xor_sync(0xffffffffu, mx0, 2));
            mx1 = fmaxf(mx1, __shfl_xor_sync(0xffffffffu, mx1, 1));
            mx1 = fmaxf(mx1, __shfl_xor_sync(0xffffffffu, mx1, 2));

            float c0 = __expf(m0 - mx0);
            float c1 = __expf(m1 - mx1);
            m0 = mx0; m1 = mx1;
            l0 *= c0;  l1 *= c1;
#pragma unroll
            for (int nt = 0; nt < 8; nt++) {
                o[nt][0] *= c0; o[nt][1] *= c0;
                o[nt][2] *= c1; o[nt][3] *= c1;
            }

            float ps0 = 0.f, ps1 = 0.f;
#pragma unroll
            for (int nt = 0; nt < 8; nt++) {
                s[nt][0] = __expf(s[nt][0] - mx0);
                s[nt][1] = __expf(s[nt][1] - mx0);
                s[nt][2] = __expf(s[nt][2] - mx1);
                s[nt][3] = __expf(s[nt][3] - mx1);
                ps0 += s[nt][0] + s[nt][1];
                ps1 += s[nt][2] + s[nt][3];
            }
            ps0 += __shfl_xor_sync(0xffffffffu, ps0, 1);
            ps0 += __shfl_xor_sync(0xffffffffu, ps0, 2);
            ps1 += __shfl_xor_sync(0xffffffffu, ps1, 1);
            ps1 += __shfl_xor_sync(0xffffffffu, ps1, 2);
            l0 += ps0; l1 += ps1;

#pragma unroll
            for (int nt = 0; nt < 8; nt++) {
                APS(r0+gid,   nt*4+tig) = f2h2(s[nt][0], s[nt][1]);
                APS(r0+gid+8, nt*4+tig) = f2h2(s[nt][2], s[nt][3]);
            }
            __syncwarp();

#pragma unroll
            for (int ks = 0; ks < 4; ks++) {
                uint32_t a0 = APS(r0+gid,   ks*8+tig);
                uint32_t a1 = APS(r0+gid+8, ks*8+tig);
                uint32_t a2 = APS(r0+gid,   ks*8+tig+4);
                uint32_t a3 = APS(r0+gid+8, ks*8+tig+4);
#pragma unroll
                for (int nt = 0; nt < 8; nt++) {
                    uint32_t b0 = AVS(buf, nt*8+gid, ks*8+tig);
                    uint32_t b1 = AVS(buf, nt*8+gid, ks*8+tig+4);
                    mma_f16(o[nt][0], o[nt][1], o[nt][2], o[nt][3],
                            a0, a1, a2, a3, b0, b1);
                }
            }
        }
        __syncthreads();             // protect buf before reissue at kt+1
    }

    float i0 = 1.0f / l0, i1 = 1.0f / l1;
    uint32_t* y0 = g_y + (((size_t)(b*SEQ + row0)) * NH + h) * (HD/2);
    uint32_t* y1 = g_y + (((size_t)(b*SEQ + row1)) * NH + h) * (HD/2);
#pragma unroll
    for (int nt = 0; nt < 8; nt++) {
        y0[nt*4+tig] = f2h2(o[nt][0] * i0, o[nt][1] * i0);
        y1[nt*4+tig] = f2h2(o[nt][2] * i1, o[nt][3] * i1);
    }
}

// ---------------- launch ----------------------------------------------------
extern "C" void kernel_launch(void* const* d_in, const int* in_sizes, int n_in,
                              void* d_out, int out_size)
{
    const float* x  = (const float*)d_in[0];
    const float* wq = (const float*)d_in[1];
    const float* wk = (const float*)d_in[2];
    const float* wv = (const float*)d_in[3];
    const float* wo = (const float*)d_in[4];
    float* out = (float*)d_out;

    uint32_t *xh, *wqkvT, *woT, *yy;
    float *qkv;
    cudaGetSymbolAddress((void**)&xh,    g_xh);
    cudaGetSymbolAddress((void**)&qkv,   g_qkv);
    cudaGetSymbolAddress((void**)&wqkvT, g_wqkvT);
    cudaGetSymbolAddress((void**)&woT,   g_woT);
    cudaGetSymbolAddress((void**)&yy,    g_y);

    static bool init_done = false;
    static cudaStream_t s1;
    static cudaEvent_t e_fork, e_wt, e_wo;
    if (!init_done) {
        cudaStreamCreateWithFlags(&s1, cudaStreamNonBlocking);
        cudaEventCreateWithFlags(&e_fork, cudaEventDisableTiming);
        cudaEventCreateWithFlags(&e_wt,   cudaEventDisableTiming);
        cudaEventCreateWithFlags(&e_wo,   cudaEventDisableTiming);
        cudaFuncSetAttribute(mma_gemm_kernel, cudaFuncAttributeMaxDynamicSharedMemorySize, GEMM_SMEM);
        cudaFuncSetAttribute(attn_mma_kernel, cudaFuncAttributeMaxDynamicSharedMemorySize, ATTN_SMEM);
        init_done = true;
    }

    cudaEventRecord(e_fork, 0);
    cudaStreamWaitEvent(s1, e_fork, 0);

    xconv_kernel<<<TOK*CDIM/(256*4), 256>>>(x);

    transpose_kernel<<<dim3(32,32), dim3(32,8), 0, s1>>>(wq, (__half*)wqkvT,               CDIM, CDIM);
    transpose_kernel<<<dim3(8, 32), dim3(32,8), 0, s1>>>(wk, (__half*)(wqkvT + 1024*GKW),  CDIM, NHKV*HD);
    transpose_kernel<<<dim3(8, 32), dim3(32,8), 0, s1>>>(wv, (__half*)(wqkvT + 1280*GKW),  CDIM, NHKV*HD);
    cudaEventRecord(e_wt, s1);
    transpose_kernel<<<dim3(32,32), dim3(32,8), 0, s1>>>(wo, (__half*)woT,                 CDIM, CDIM);
    cudaEventRecord(e_wo, s1);

    cudaStreamWaitEvent(0, e_wt, 0);

    mma_gemm_kernel<<<dim3(NQKV/128, TOK/128), 256, GEMM_SMEM>>>(xh, wqkvT, qkv, NQKV);

    pack_kernel<<<(TOK*20)/8, 256>>>();
    vtrans_kernel<<<dim3(SEQ/32, HD/32, BATCH*NHKV), dim3(32,8)>>>();

    attn_mma_kernel<<<dim3(SEQ/128, NH, BATCH), 256, ATTN_SMEM>>>();

    cudaStreamWaitEvent(0, e_wo, 0);
    mma_gemm_kernel<<<dim3(CDIM/128, TOK/128), 256, GEMM_SMEM>>>(yy, woT, out, CDIM);
}